// round 15
// baseline (speedup 1.0000x reference)
#include <cuda_runtime.h>
#include <cuda_fp16.h>
#include <stdint.h>

#define HEADS 12
#define HD 64
#define DIMC 768
#define NB 4
#define NN 1024
#define LDQKV (3 * DIMC)
#define ATT_SCALE 0.125f
#define NZ (NB * HEADS)

// ---------------- global scratch ----------------
__device__ int8_t g_xih[(size_t)NB * NN * DIMC], g_xil[(size_t)NB * NN * DIMC];
__device__ float  g_xs[NB * NN];
__device__ int8_t g_wih[(size_t)3 * DIMC * DIMC], g_wil[(size_t)3 * DIMC * DIMC];
__device__ float  g_ws[3 * DIMC];
__device__ float  g_qkvf[(size_t)NB * NN * LDQKV];      // only V region used now
__device__ int8_t g_qih[(size_t)NZ * NN * HD], g_qil[(size_t)NZ * NN * HD];
__device__ float  g_qs[NZ * NN];
__device__ int8_t g_kih[(size_t)NZ * NN * HD], g_kil[(size_t)NZ * NN * HD];
__device__ float  g_ks[NZ * NN];
__device__ __half g_Sh[(size_t)NZ * NN * NN];           // fp16 scores
__device__ int8_t g_Aih[(size_t)NZ * NN * NN], g_Ail[(size_t)NZ * NN * NN];
__device__ float  g_As[NZ * NN];
__device__ int8_t g_vTih[(size_t)NZ * HD * NN], g_vTil[(size_t)NZ * HD * NN];
__device__ float  g_vTs[NZ * HD];
__device__ unsigned g_vTmax[NZ * HD];
__device__ float  g_Av[(size_t)NZ * NN * HD];
__device__ int8_t g_AvTih[(size_t)NZ * HD * NN], g_AvTil[(size_t)NZ * HD * NN];
__device__ float  g_AvTs[NZ * HD];
__device__ unsigned g_AvTmax[NZ * HD];
__device__ float  g_O[(size_t)NB * NN * DIMC];
__device__ int8_t g_Oih[(size_t)NB * NN * DIMC], g_Oil[(size_t)NB * NN * DIMC];
__device__ float  g_Os[NB * NN];
__device__ int8_t g_woih[(size_t)DIMC * DIMC], g_woil[(size_t)DIMC * DIMC];
__device__ float  g_wos[DIMC];

// ---------------- helpers ----------------
__device__ __forceinline__ void imma16832(int *c, const uint32_t *a, const uint32_t *b) {
    asm volatile(
        "mma.sync.aligned.m16n8k32.row.col.s32.s8.s8.s32 "
        "{%0,%1,%2,%3},{%4,%5,%6,%7},{%8,%9},{%0,%1,%2,%3};"
        : "+r"(c[0]), "+r"(c[1]), "+r"(c[2]), "+r"(c[3])
        : "r"(a[0]), "r"(a[1]), "r"(a[2]), "r"(a[3]), "r"(b[0]), "r"(b[1]));
}
__device__ __forceinline__ void ldm_x4(uint32_t (&r)[4], uint32_t a) {
    asm volatile("ldmatrix.sync.aligned.m8n8.x4.shared.b16 {%0,%1,%2,%3}, [%4];"
                 : "=r"(r[0]), "=r"(r[1]), "=r"(r[2]), "=r"(r[3]) : "r"(a));
}
__device__ __forceinline__ void ldm_x2(uint32_t (&r)[2], uint32_t a) {
    asm volatile("ldmatrix.sync.aligned.m8n8.x2.shared.b16 {%0,%1}, [%2];"
                 : "=r"(r[0]), "=r"(r[1]) : "r"(a));
}
__device__ __forceinline__ void cpa16(uint32_t s, const void *g) {
    asm volatile("cp.async.cg.shared.global [%0], [%1], 16;" :: "r"(s), "l"(g));
}
__device__ __forceinline__ void cpa_commit() { asm volatile("cp.async.commit_group;"); }

// ================= int8 NT engine core, BM=128 x BN=128, BK=32, 512 thr =================
template <int NSTAGE>
__device__ __forceinline__ void gemm_i8_128(
    const int8_t* Ah_, const int8_t* Al_, int lda,
    const int8_t* Bh_, const int8_t* Bl_, int ldb,
    int K, int (&hh)[2][4][4], int (&cx)[2][4][4])
{
    extern __shared__ __align__(16) int8_t smi[];
    const uint32_t sb = (uint32_t)__cvta_generic_to_shared(smi);
    const int t = threadIdx.x, lane = t & 31, wid = t >> 5;
    const int wm = wid >> 2, wn = wid & 3;

    const int lrow = (t >> 1) & 127, lseg = t & 1, lps = t >> 8;
    const int8_t* pA = (lps ? Al_ : Ah_) + (size_t)lrow * lda + lseg * 16;
    const int8_t* pB = (lps ? Bl_ : Bh_) + (size_t)lrow * ldb + lseg * 16;
    const uint32_t aoff = (uint32_t)(lps * 6144 + lrow * 48 + lseg * 16);
    const uint32_t boff = 12288u + (uint32_t)(lps * 6144 + lrow * 48 + lseg * 16);

    const int nst = K >> 5;
    auto issue = [&](int i) {
        const uint32_t s0 = sb + (uint32_t)(i & (NSTAGE - 1)) * 24576;
        cpa16(s0 + aoff, pA + i * 32);
        cpa16(s0 + boff, pB + i * 32);
        cpa_commit();
    };

    issue(0);
    if (nst > 1) issue(1);
    if (NSTAGE > 2 && nst > 2) issue(2);

    for (int i = 0; i < nst; i++) {
        if (NSTAGE > 2 && i + 3 < nst) {
            issue(i + 3);
            asm volatile("cp.async.wait_group 3;");
        } else {
            const int rem = nst - 1 - i;
            if (rem >= 2)      asm volatile("cp.async.wait_group 2;");
            else if (rem == 1) asm volatile("cp.async.wait_group 1;");
            else               asm volatile("cp.async.wait_group 0;");
        }
        __syncthreads();
        const uint32_t sA = sb + (uint32_t)(i & (NSTAGE - 1)) * 24576;
        const uint32_t sB = sA + 12288;
        uint32_t ah[2][4], al[2][4];
#pragma unroll
        for (int mf = 0; mf < 2; mf++) {
            const int m0 = wm * 32 + mf * 16;
            const uint32_t ad = sA + (uint32_t)((m0 + (lane & 15)) * 48) + ((lane >> 4) & 1) * 16;
            ldm_x4(ah[mf], ad);
            ldm_x4(al[mf], ad + 6144);
        }
#pragma unroll
        for (int nf = 0; nf < 4; nf++) {
            const int n0 = wn * 32 + nf * 8;
            const uint32_t bd = sB + (uint32_t)((n0 + (lane & 7)) * 48) + ((lane >> 3) & 1) * 16;
            uint32_t bh[2], bl[2];
            ldm_x2(bh, bd);
            ldm_x2(bl, bd + 6144);
#pragma unroll
            for (int mf = 0; mf < 2; mf++) {
                imma16832(hh[mf][nf], ah[mf], bh);
                imma16832(cx[mf][nf], ah[mf], bl);
                imma16832(cx[mf][nf], al[mf], bh);
            }
        }
        __syncthreads();
    }
}

// ================= int8 NT engine, BN=64: BM=128, BK=32, 4-stage, 256 thr =================
__device__ __forceinline__ void gemm_i8_64(
    const int8_t* Agh, const int8_t* Agl,
    const int8_t* Bgh, const int8_t* Bgl,
    int K, int (&hh)[2][4][4], int (&cx)[2][4][4])
{
    extern __shared__ __align__(16) int8_t smi[];
    const uint32_t sb = (uint32_t)__cvta_generic_to_shared(smi);
    const int t = threadIdx.x, lane = t & 31, wid = t >> 5;
    const int wm = wid >> 1, wn = wid & 1;

    const int arow = t >> 1, aseg = t & 1;
    const int brow = t & 63, bseg = (t >> 6) & 1, bpl = (t >> 7) & 1;
    const int8_t* pAh = Agh + (size_t)arow * K + aseg * 16;
    const int8_t* pAl = Agl + (size_t)arow * K + aseg * 16;
    const int8_t* pB  = (bpl ? Bgl : Bgh) + (size_t)brow * K + bseg * 16;
    const uint32_t aoff = (uint32_t)(arow * 48 + aseg * 16);
    const uint32_t boff = 12288u + (uint32_t)(bpl * 3072 + brow * 48 + bseg * 16);

    const int nst = K >> 5;
    auto issue = [&](int i) {
        const uint32_t s0 = sb + (uint32_t)(i & 3) * 18432;
        const int k0 = i * 32;
        cpa16(s0 + aoff,        pAh + k0);
        cpa16(s0 + 6144 + aoff, pAl + k0);
        cpa16(s0 + boff,        pB + k0);
        cpa_commit();
    };

    issue(0); issue(1); issue(2);

    for (int i = 0; i < nst; i++) {
        if (i + 3 < nst) {
            issue(i + 3);
            asm volatile("cp.async.wait_group 3;");
        } else {
            const int rem = nst - 1 - i;
            if (rem == 2)      asm volatile("cp.async.wait_group 2;");
            else if (rem == 1) asm volatile("cp.async.wait_group 1;");
            else               asm volatile("cp.async.wait_group 0;");
        }
        __syncthreads();
        const uint32_t sA = sb + (uint32_t)(i & 3) * 18432;
        const uint32_t sB = sA + 12288;
        uint32_t ah[2][4], al[2][4];
#pragma unroll
        for (int mf = 0; mf < 2; mf++) {
            const int m0 = wm * 32 + mf * 16;
            const uint32_t ad = sA + (uint32_t)((m0 + (lane & 15)) * 48) + ((lane >> 4) & 1) * 16;
            ldm_x4(ah[mf], ad);
            ldm_x4(al[mf], ad + 6144);
        }
#pragma unroll
        for (int nf = 0; nf < 4; nf++) {
            const int n0 = wn * 32 + nf * 8;
            const uint32_t bd = sB + (uint32_t)((n0 + (lane & 7)) * 48) + ((lane >> 3) & 1) * 16;
            uint32_t bh[2], bl[2];
            ldm_x2(bh, bd);
            ldm_x2(bl, bd + 3072);
#pragma unroll
            for (int mf = 0; mf < 2; mf++) {
                imma16832(hh[mf][nf], ah[mf], bh);
                imma16832(cx[mf][nf], ah[mf], bl);
                imma16832(cx[mf][nf], al[mf], bh);
            }
        }
        __syncthreads();
    }
}

// ---------------- row quantization ----------------
__global__ void __launch_bounds__(256) k_quant(const float* __restrict__ s, int K,
                                               int8_t* __restrict__ dh,
                                               int8_t* __restrict__ dl,
                                               float* __restrict__ sc)
{
    const int row = blockIdx.x;
    const float* p = s + (size_t)row * K;
    __shared__ float red[8];
    float m = 0.f;
    for (int i = threadIdx.x; i < K; i += 256) m = fmaxf(m, fabsf(p[i]));
#pragma unroll
    for (int o = 16; o; o >>= 1) m = fmaxf(m, __shfl_xor_sync(0xffffffffu, m, o));
    if ((threadIdx.x & 31) == 0) red[threadIdx.x >> 5] = m;
    __syncthreads();
    if (threadIdx.x == 0) {
        float v = red[0];
#pragma unroll
        for (int w = 1; w < 8; w++) v = fmaxf(v, red[w]);
        red[0] = v;
        sc[row] = v * (1.f / 16256.f);
    }
    __syncthreads();
    const float mx = red[0];
    const float inv = mx > 0.f ? 16256.f / mx : 0.f;
    for (int i = threadIdx.x; i < K; i += 256) {
        float q = p[i] * inv;
        float hf = rintf(q * (1.f / 128.f));
        float lf = rintf(q - 128.f * hf);
        dh[(size_t)row * K + i] = (int8_t)hf;
        dl[(size_t)row * K + i] = (int8_t)lf;
    }
}

// ---------------- transpose-quant of V / Av (two-phase) ----------------
__device__ __forceinline__ float tq_read(int mode, int z, int b, int h, int m, int d) {
    if (mode == 0)
        return g_qkvf[((size_t)b * NN + m) * LDQKV + 2 * DIMC + h * HD + d];
    return g_Av[((size_t)z * NN + m) * HD + d];
}

__global__ void __launch_bounds__(256) k_tqmax(int mode, unsigned* __restrict__ gmax)
{
    const int z = blockIdx.y, b = z / HEADS, h = z % HEADS;
    const int mt0 = blockIdx.x * 128;
    __shared__ float red4[4][64];
    const int t = threadIdx.x, d = t & 63, mg = t >> 6;
    float mx = 0.f;
    for (int m = mt0 + mg; m < mt0 + 128; m += 4)
        mx = fmaxf(mx, fabsf(tq_read(mode, z, b, h, m, d)));
    red4[mg][d] = mx;
    __syncthreads();
    if (t < 64) {
        float m2 = fmaxf(fmaxf(red4[0][t], red4[1][t]), fmaxf(red4[2][t], red4[3][t]));
        atomicMax(&gmax[z * HD + t], __float_as_uint(m2));
    }
}

__global__ void __launch_bounds__(256) k_tqq(int mode, const unsigned* __restrict__ gmax)
{
    const int z = blockIdx.y, b = z / HEADS, h = z % HEADS;
    const int mt0 = blockIdx.x * 128;
    __shared__ float sinv[64];
    __shared__ float tile[64][65];
    const int t = threadIdx.x, d = t & 63, mg = t >> 6;

    if (t < 64) {
        float m2 = __uint_as_float(gmax[z * HD + t]);
        sinv[t] = m2 > 0.f ? 16256.f / m2 : 0.f;
        if (blockIdx.x == 0)
            (mode ? g_AvTs : g_vTs)[z * HD + t] = m2 * (1.f / 16256.f);
    }
    __syncthreads();

    int8_t* oh = mode ? g_AvTih : g_vTih;
    int8_t* ol = mode ? g_AvTil : g_vTil;
    const int dd = t >> 2, seg = t & 3;
    for (int mt = mt0; mt < mt0 + 128; mt += 64) {
#pragma unroll 4
        for (int k = 0; k < 16; k++) {
            const int ml = mg + 4 * k;
            tile[ml][d] = tq_read(mode, z, b, h, mt + ml, d);
        }
        __syncthreads();
        __align__(16) int8_t hb[16], lb[16];
        const float inv = sinv[dd];
#pragma unroll
        for (int j = 0; j < 16; j++) {
            float q = tile[seg * 16 + j][dd] * inv;
            float hf = rintf(q * (1.f / 128.f));
            float lf = rintf(q - 128.f * hf);
            hb[j] = (int8_t)hf; lb[j] = (int8_t)lf;
        }
        const size_t off = ((size_t)z * HD + dd) * NN + mt + seg * 16;
        *(int4*)&oh[off] = *(const int4*)hb;
        *(int4*)&ol[off] = *(const int4*)lb;
        __syncthreads();
    }
}

// ================= qkv = x @ qkv_w^T; q/k quantized in-epilogue, V -> fp32 =================
__global__ void __launch_bounds__(512, 1) k_qkv_i8()
{
    __shared__ int   smax_i[128][2];
    __shared__ float sminv[128][2];
    const int row0 = blockIdx.y * 128, col0 = blockIdx.x * 128;
    int hh[2][4][4] = {}, cx[2][4][4] = {};
    gemm_i8_128<4>(g_xih + (size_t)row0 * DIMC, g_xil + (size_t)row0 * DIMC, DIMC,
                   g_wih + (size_t)col0 * DIMC, g_wil + (size_t)col0 * DIMC, DIMC,
                   DIMC, hh, cx);
    const int t = threadIdx.x;
    const int lane = t & 31, wid = t >> 5;
    const int wm = wid >> 2, wn = wid & 3, g = lane >> 2, tig = lane & 3;
    const int which = (col0 < DIMC) ? 0 : ((col0 < 2 * DIMC) ? 1 : 2);

    if (which == 2) {
#pragma unroll
        for (int mf = 0; mf < 2; mf++) {
            const int row = row0 + wm * 32 + mf * 16 + g;
            const float sr0 = g_xs[row], sr1 = g_xs[row + 8];
#pragma unroll
            for (int nf = 0; nf < 4; nf++) {
                const int col = col0 + wn * 32 + nf * 8 + tig * 2;
                const float sc0 = g_ws[col], sc1 = g_ws[col + 1];
                *(float2*)&g_qkvf[(size_t)row * LDQKV + col] = make_float2(
                    sr0 * sc0 * (16384.f * (float)hh[mf][nf][0] + 128.f * (float)cx[mf][nf][0]),
                    sr0 * sc1 * (16384.f * (float)hh[mf][nf][1] + 128.f * (float)cx[mf][nf][1]));
                *(float2*)&g_qkvf[(size_t)(row + 8) * LDQKV + col] = make_float2(
                    sr1 * sc0 * (16384.f * (float)hh[mf][nf][2] + 128.f * (float)cx[mf][nf][2]),
                    sr1 * sc1 * (16384.f * (float)hh[mf][nf][3] + 128.f * (float)cx[mf][nf][3]));
            }
        }
        return;
    }

    const float qsc = which ? 1.f : ATT_SCALE;
    const int half = wn >> 1;
    const int dbase = (wn & 1) * 32;

    if (t < 256) { smax_i[t >> 1][t & 1] = 0; }
    __syncthreads();

#pragma unroll
    for (int mf = 0; mf < 2; mf++) {
        const int rloc = wm * 32 + mf * 16 + g;
        const float sr0 = g_xs[row0 + rloc] * qsc, sr1 = g_xs[row0 + rloc + 8] * qsc;
        float m0 = 0.f, m1 = 0.f;
#pragma unroll
        for (int nf = 0; nf < 4; nf++) {
            const int col = col0 + wn * 32 + nf * 8 + tig * 2;
            const float sc0 = g_ws[col], sc1 = g_ws[col + 1];
            m0 = fmaxf(m0, fabsf(sr0 * sc0 * (16384.f * (float)hh[mf][nf][0] + 128.f * (float)cx[mf][nf][0])));
            m0 = fmaxf(m0, fabsf(sr0 * sc1 * (16384.f * (float)hh[mf][nf][1] + 128.f * (float)cx[mf][nf][1])));
            m1 = fmaxf(m1, fabsf(sr1 * sc0 * (16384.f * (float)hh[mf][nf][2] + 128.f * (float)cx[mf][nf][2])));
            m1 = fmaxf(m1, fabsf(sr1 * sc1 * (16384.f * (float)hh[mf][nf][3] + 128.f * (float)cx[mf][nf][3])));
        }
        atomicMax(&smax_i[rloc][half],     __float_as_int(m0));
        atomicMax(&smax_i[rloc + 8][half], __float_as_int(m1));
    }
    __syncthreads();

    const int head2 = (col0 - which * DIMC) >> 6;
    if (t < 256) {
        const int r = t >> 1, hf = t & 1;
        const float mx = __int_as_float(smax_i[r][hf]);
        const int grow = row0 + r, b = grow >> 10, n = grow & 1023;
        const int z = b * HEADS + head2 + hf;
        (which ? g_ks : g_qs)[z * NN + n] = mx * (1.f / 16256.f);
        sminv[r][hf] = mx > 0.f ? 16256.f / mx : 0.f;
    }
    __syncthreads();

    int8_t* dh = which ? g_kih : g_qih;
    int8_t* dl = which ? g_kil : g_qil;
#pragma unroll
    for (int mf = 0; mf < 2; mf++) {
        const int rloc = wm * 32 + mf * 16 + g;
        const float sr0 = g_xs[row0 + rloc] * qsc, sr1 = g_xs[row0 + rloc + 8] * qsc;
        const float inv0 = sminv[rloc][half], inv1 = sminv[rloc + 8][half];
        const int grow0 = row0 + rloc;
        const int b0 = grow0 >> 10, n0 = grow0 & 1023;
        const int z = b0 * HEADS + head2 + half;
        const size_t base0 = ((size_t)z * NN + n0) * HD;
        const size_t base1 = ((size_t)z * NN + n0 + 8) * HD;
#pragma unroll
        for (int nf = 0; nf < 4; nf++) {
            const int col = col0 + wn * 32 + nf * 8 + tig * 2;
            const int d = dbase + nf * 8 + tig * 2;
            const float sc0 = g_ws[col], sc1 = g_ws[col + 1];
            const float v00 = sr0 * sc0 * (16384.f * (float)hh[mf][nf][0] + 128.f * (float)cx[mf][nf][0]);
            const float v01 = sr0 * sc1 * (16384.f * (float)hh[mf][nf][1] + 128.f * (float)cx[mf][nf][1]);
            const float v10 = sr1 * sc0 * (16384.f * (float)hh[mf][nf][2] + 128.f * (float)cx[mf][nf][2]);
            const float v11 = sr1 * sc1 * (16384.f * (float)hh[mf][nf][3] + 128.f * (float)cx[mf][nf][3]);
            float q0 = v00 * inv0, q1 = v01 * inv0, q2 = v10 * inv1, q3 = v11 * inv1;
            float h0 = rintf(q0 * (1.f / 128.f)), h1 = rintf(q1 * (1.f / 128.f));
            float h2 = rintf(q2 * (1.f / 128.f)), h3 = rintf(q3 * (1.f / 128.f));
            *(char2*)&dh[base0 + d] = make_char2((signed char)h0, (signed char)h1);
            *(char2*)&dl[base0 + d] = make_char2((signed char)rintf(q0 - 128.f * h0),
                                                 (signed char)rintf(q1 - 128.f * h1));
            *(char2*)&dh[base1 + d] = make_char2((signed char)h2, (signed char)h3);
            *(char2*)&dl[base1 + d] = make_char2((signed char)rintf(q2 - 128.f * h2),
                                                 (signed char)rintf(q3 - 128.f * h3));
        }
    }
}

// ================= scores: persistent-q, fp16 S output =================
__global__ void __launch_bounds__(512, 1) k_scores_i8()
{
    extern __shared__ __align__(16) int8_t smi[];
    const uint32_t sb = (uint32_t)__cvta_generic_to_shared(smi);
    const int t = threadIdx.x, lane = t & 31, wid = t >> 5;
    const int wm = wid >> 2, wn = wid & 3;
    const int z = blockIdx.y;
    const int row0 = blockIdx.x * 128;

    const int qrow = t >> 2, qseg = t & 3;
    {
        const size_t src = ((size_t)z * NN + row0 + qrow) * HD + qseg * 16;
        const uint32_t d = sb + (uint32_t)(qrow * 80 + qseg * 16);
        cpa16(d,         g_qih + src);
        cpa16(d + 10240, g_qil + src);
    }
    cpa_commit();
    auto kissue = [&](int ct) {
        const size_t src = ((size_t)z * NN + ct * 128 + qrow) * HD + qseg * 16;
        const uint32_t d = sb + 20480 + (uint32_t)((ct & 1) * 20480 + qrow * 80 + qseg * 16);
        cpa16(d,         g_kih + src);
        cpa16(d + 10240, g_kil + src);
        cpa_commit();
    };
    kissue(0);

    asm volatile("cp.async.wait_group 1;");
    __syncthreads();
    uint32_t qah[2][2][4], qal[2][2][4];
#pragma unroll
    for (int s2 = 0; s2 < 2; s2++)
#pragma unroll
        for (int mf = 0; mf < 2; mf++) {
            const int m0 = wm * 32 + mf * 16;
            const uint32_t ad = sb + (uint32_t)((m0 + (lane & 15)) * 80) + s2 * 32 + ((lane >> 4) & 1) * 16;
            ldm_x4(qah[s2][mf], ad);
            ldm_x4(qal[s2][mf], ad + 10240);
        }

    const float* sq = g_qs + (size_t)z * NN;
    const float* sk = g_ks + (size_t)z * NN;
    __half* S = g_Sh + (size_t)z * NN * NN;
    const int g = lane >> 2, tig = lane & 3;

    for (int ct = 0; ct < 8; ct++) {
        if (ct + 1 < 8) { kissue(ct + 1); asm volatile("cp.async.wait_group 1;"); }
        else asm volatile("cp.async.wait_group 0;");
        __syncthreads();
        int hh[2][4][4] = {}, cx[2][4][4] = {};
        const uint32_t sK = sb + 20480 + (uint32_t)((ct & 1) * 20480);
#pragma unroll
        for (int s2 = 0; s2 < 2; s2++) {
#pragma unroll
            for (int nf = 0; nf < 4; nf++) {
                const int n0 = wn * 32 + nf * 8;
                const uint32_t bd = sK + (uint32_t)((n0 + (lane & 7)) * 80) + s2 * 32 + ((lane >> 3) & 1) * 16;
                uint32_t bh[2], bl[2];
                ldm_x2(bh, bd);
                ldm_x2(bl, bd + 10240);
#pragma unroll
                for (int mf = 0; mf < 2; mf++) {
                    imma16832(hh[mf][nf], qah[s2][mf], bh);
                    imma16832(cx[mf][nf], qah[s2][mf], bl);
                    imma16832(cx[mf][nf], qal[s2][mf], bh);
                }
            }
        }
        __syncthreads();
        const int col0 = ct * 128;
#pragma unroll
        for (int mf = 0; mf < 2; mf++) {
            const int row = row0 + wm * 32 + mf * 16 + g;
            const float sr0 = sq[row], sr1 = sq[row + 8];
#pragma unroll
            for (int nf = 0; nf < 4; nf++) {
                const int col = col0 + wn * 32 + nf * 8 + tig * 2;
                const float sc0 = sk[col], sc1 = sk[col + 1];
                *(__half2*)&S[(size_t)row * NN + col] = __floats2half2_rn(
                    sr0 * sc0 * (16384.f * (float)hh[mf][nf][0] + 128.f * (float)cx[mf][nf][0]),
                    sr0 * sc1 * (16384.f * (float)hh[mf][nf][1] + 128.f * (float)cx[mf][nf][1]));
                *(__half2*)&S[(size_t)(row + 8) * NN + col] = __floats2half2_rn(
                    sr1 * sc0 * (16384.f * (float)hh[mf][nf][2] + 128.f * (float)cx[mf][nf][2]),
                    sr1 * sc1 * (16384.f * (float)hh[mf][nf][3] + 128.f * (float)cx[mf][nf][3]));
            }
        }
    }
}

// ================= out = O @ Wout^T + bias =================
__global__ void __launch_bounds__(512, 1) k_out_i8(const float* __restrict__ bias,
                                                   float* __restrict__ out)
{
    const int row0 = blockIdx.y * 128, col0 = blockIdx.x * 128;
    int hh[2][4][4] = {}, cx[2][4][4] = {};
    gemm_i8_128<4>(g_Oih + (size_t)row0 * DIMC, g_Oil + (size_t)row0 * DIMC, DIMC,
                   g_woih + (size_t)col0 * DIMC, g_woil + (size_t)col0 * DIMC, DIMC,
                   DIMC, hh, cx);
    const int lane = threadIdx.x & 31, wid = threadIdx.x >> 5;
    const int wm = wid >> 2, wn = wid & 3, g = lane >> 2, tig = lane & 3;
#pragma unroll
    for (int mf = 0; mf < 2; mf++) {
        const int row = row0 + wm * 32 + mf * 16 + g;
        const float sr0 = g_Os[row], sr1 = g_Os[row + 8];
#pragma unroll
        for (int nf = 0; nf < 4; nf++) {
            const int col = col0 + wn * 32 + nf * 8 + tig * 2;
            const float sc0 = g_wos[col], sc1 = g_wos[col + 1];
            const float b0 = bias[col], b1 = bias[col + 1];
            *(float2*)&out[(size_t)row * DIMC + col] = make_float2(
                fmaf(sr0 * sc0, 16384.f * (float)hh[mf][nf][0] + 128.f * (float)cx[mf][nf][0], b0),
                fmaf(sr0 * sc1, 16384.f * (float)hh[mf][nf][1] + 128.f * (float)cx[mf][nf][1], b1));
            *(float2*)&out[(size_t)(row + 8) * DIMC + col] = make_float2(
                fmaf(sr1 * sc0, 16384.f * (float)hh[mf][nf][2] + 128.f * (float)cx[mf][nf][2], b0),
                fmaf(sr1 * sc1, 16384.f * (float)hh[mf][nf][3] + 128.f * (float)cx[mf][nf][3], b1));
        }
    }
}

// ---------------- int8 A@V and A@(A@V) ----------------
__global__ void __launch_bounds__(256, 2) k_av_i8()
{
    const int z = blockIdx.z;
    const int row0 = blockIdx.y * 128;
    int hh[2][4][4] = {}, cx[2][4][4] = {};
    gemm_i8_64(g_Aih + (size_t)z * NN * NN + (size_t)row0 * NN,
               g_Ail + (size_t)z * NN * NN + (size_t)row0 * NN,
               g_vTih + (size_t)z * HD * NN,
               g_vTil + (size_t)z * HD * NN, NN, hh, cx);
    const int lane = threadIdx.x & 31, wid = threadIdx.x >> 5;
    const int wm = wid >> 1, wn = wid & 1, g = lane >> 2, tig = lane & 3;
    float* Av = g_Av + (size_t)z * NN * HD;
#pragma unroll
    for (int mf = 0; mf < 2; mf++) {
        const int row = row0 + wm * 32 + mf * 16 + g;
        const float sr0 = g_As[(size_t)z * NN + row], sr1 = g_As[(size_t)z * NN + row + 8];
#pragma unroll
        for (int nf = 0; nf < 4; nf++) {
            const int col = wn * 32 + nf * 8 + tig * 2;
            const float sc0 = g_vTs[z * HD + col], sc1 = g_vTs[z * HD + col + 1];
            *(float2*)&Av[(size_t)row * HD + col] = make_float2(
                sr0 * sc0 * (16384.f * (float)hh[mf][nf][0] + 128.f * (float)cx[mf][nf][0]),
                sr0 * sc1 * (16384.f * (float)hh[mf][nf][1] + 128.f * (float)cx[mf][nf][1]));
            *(float2*)&Av[(size_t)(row + 8) * HD + col] = make_float2(
                sr1 * sc0 * (16384.f * (float)hh[mf][nf][2] + 128.f * (float)cx[mf][nf][2]),
                sr1 * sc1 * (16384.f * (float)hh[mf][nf][3] + 128.f * (float)cx[mf][nf][3]));
        }
    }
}

__global__ void __launch_bounds__(256, 2) k_aav_i8(const float* __restrict__ lamb)
{
    const int z = blockIdx.z, b = z / HEADS, h = z % HEADS;
    const int row0 = blockIdx.y * 128;
    int hh[2][4][4] = {}, cx[2][4][4] = {};
    gemm_i8_64(g_Aih + (size_t)z * NN * NN + (size_t)row0 * NN,
               g_Ail + (size_t)z * NN * NN + (size_t)row0 * NN,
               g_AvTih + (size_t)z * HD * NN,
               g_AvTil + (size_t)z * HD * NN, NN, hh, cx);
    const float lam = lamb[h];
    const float c1 = 1.f - 2.f * lam, c3 = 3.f * lam;
    const int lane = threadIdx.x & 31, wid = threadIdx.x >> 5;
    const int wm = wid >> 1, wn = wid & 1, g = lane >> 2, tig = lane & 3;
    const float* Av = g_Av + (size_t)z * NN * HD;
#pragma unroll
    for (int mf = 0; mf < 2; mf++) {
        const int row = row0 + wm * 32 + mf * 16 + g;
        const float sr0 = g_As[(size_t)z * NN + row], sr1 = g_As[(size_t)z * NN + row + 8];
#pragma unroll
        for (int nf = 0; nf < 4; nf++) {
            const int col = wn * 32 + nf * 8 + tig * 2;
            const float sc0 = g_AvTs[z * HD + col], sc1 = g_AvTs[z * HD + col + 1];
            const float r00 = sr0 * sc0 * (16384.f * (float)hh[mf][nf][0] + 128.f * (float)cx[mf][nf][0]);
            const float r01 = sr0 * sc1 * (16384.f * (float)hh[mf][nf][1] + 128.f * (float)cx[mf][nf][1]);
            const float r10 = sr1 * sc0 * (16384.f * (float)hh[mf][nf][2] + 128.f * (float)cx[mf][nf][2]);
            const float r11 = sr1 * sc1 * (16384.f * (float)hh[mf][nf][3] + 128.f * (float)cx[mf][nf][3]);
            float2 av0 = *(const float2*)&Av[(size_t)row * HD + col];
            float2 av1 = *(const float2*)&Av[(size_t)(row + 8) * HD + col];
            const size_t oi0 = ((size_t)b * NN + row) * DIMC + h * HD + col;
            const size_t oi1 = ((size_t)b * NN + row + 8) * DIMC + h * HD + col;
            *(float2*)&g_O[oi0] = make_float2(fmaf(c3, r00, c1 * av0.x), fmaf(c3, r01, c1 * av0.y));
            *(float2*)&g_O[oi1] = make_float2(fmaf(c3, r10, c1 * av1.x), fmaf(c3, r11, c1 * av1.y));
        }
    }
}

// ---------------- all-register L-mix -> softmax -> W-mix -> int8 A quant ----------------
// 1024 threads, one column per thread; only cross-thread traffic is 3 block reductions.
__global__ void __launch_bounds__(1024) k_mix(const float* __restrict__ Lw,
                                              const float* __restrict__ Lb,
                                              const float* __restrict__ Ww,
                                              const float* __restrict__ Wb)
{
    __shared__ float sL[144], sW[144], sbl[12], sbw[12];
    __shared__ float red[12][32];
    __shared__ float gmax[12], ginv[12], sAinv[12];

    const int tid = threadIdx.x;
    const int b = blockIdx.x >> 10;
    const int n = blockIdx.x & 1023;

    if (tid < 144) { sL[tid] = Lw[tid]; sW[tid] = Ww[tid]; }
    if (tid < 12)  { sbl[tid] = Lb[tid]; sbw[tid] = Wb[tid]; }
    __syncthreads();

    const __half* Sbase = g_Sh + (size_t)b * HEADS * NN * NN + (size_t)n * NN;
    const int lane = tid & 31, wrp = tid >> 5;
    const int m = tid;

    float s[12];
#pragma unroll
    for (int h = 0; h < 12; h++)
        s[h] = __half2float(Sbase[(size_t)h * NN * NN + m]);

    // L-mix + per-head max
    float a[12];
#pragma unroll
    for (int g = 0; g < 12; g++) {
        float t = sbl[g];
#pragma unroll
        for (int h = 0; h < 12; h++) t = fmaf(sL[g * 12 + h], s[h], t);
        a[g] = t;
    }
#pragma unroll
    for (int g = 0; g < 12; g++) {
        float v = a[g];
#pragma unroll
        for (int o = 16; o; o >>= 1) v = fmaxf(v, __shfl_xor_sync(0xffffffffu, v, o));
        if (lane == 0) red[g][wrp] = v;
    }
    __syncthreads();
    if (tid < 12) {
        float v = red[tid][0];
#pragma unroll
        for (int w = 1; w < 32; w++) v = fmaxf(v, red[tid][w]);
        gmax[tid] = v;
    }
    __syncthreads();

    // exp + sum
#pragma unroll
    for (int g = 0; g < 12; g++) a[g] = __expf(a[g] - gmax[g]);
#pragma unroll
    for (int g = 0; g < 12; g++) {
        float v = a[g];
#pragma unroll
        for (int o = 16; o; o >>= 1) v += __shfl_xor_sync(0xffffffffu, v, o);
        if (lane == 0) red[g][wrp] = v;
    }
    __syncthreads();
    if (tid < 12) {
        float v = red[tid][0];
#pragma unroll
        for (int w = 1; w < 32; w++) v += red[tid][w];
        ginv[tid] = 1.f / v;
    }
    __syncthreads();

    // normalize + W-mix + per-head max|a|
#pragma unroll
    for (int h = 0; h < 12; h++) s[h] = a[h] * ginv[h];   // s = probabilities now
    float o12[12];
#pragma unroll
    for (int g = 0; g < 12; g++) {
        float t = sbw[g];
#pragma unroll
        for (int h = 0; h < 12; h++) t = fmaf(sW[g * 12 + h], s[h], t);
        o12[g] = t;
    }
#pragma unroll
    for (int g = 0; g < 12; g++) {
        float v = fabsf(o12[g]);
#pragma unroll
        for (int o = 16; o; o >>= 1) v = fmaxf(v, __shfl_xor_sync(0xffffffffu, v, o));
        if (lane == 0) red[g][wrp] = v;
    }
    __syncthreads();
    if (tid < 12) {
        float v = red[tid][0];
#pragma unroll
        for (int w = 1; w < 32; w++) v = fmaxf(v, red[tid][w]);
        g_As[((size_t)b * HEADS + tid) * NN + n] = v * (1.f / 16256.f);
        sAinv[tid] = v > 0.f ? 16256.f / v : 0.f;
    }
    __syncthreads();

    // quantize + store
    const size_t abase = (size_t)b * HEADS * NN * NN + (size_t)n * NN;
#pragma unroll
    for (int g = 0; g < 12; g++) {
        float q = o12[g] * sAinv[g];
        float hf = rintf(q * (1.f / 128.f));
        float lf = rintf(q - 128.f * hf);
        const size_t o = abase + (size_t)g * NN * NN + m;
        g_Aih[o] = (int8_t)hf;
        g_Ail[o] = (int8_t)lf;
    }
}

// ---------------- launch ----------------
extern "C" void kernel_launch(void* const* d_in, const int* in_sizes, int n_in,
                              void* d_out, int out_size)
{
    (void)in_sizes; (void)n_in; (void)out_size;
    const float* x      = (const float*)d_in[0];
    const float* qkv_w  = (const float*)d_in[1];
    const float* Lw     = (const float*)d_in[2];
    const float* Lb     = (const float*)d_in[3];
    const float* Ww     = (const float*)d_in[4];
    const float* Wb     = (const float*)d_in[5];
    const float* lamb   = (const float*)d_in[6];
    const float* Wout   = (const float*)d_in[7];
    const float* bout   = (const float*)d_in[8];
    float* out = (float*)d_out;

    const int I8Q_SMEM = 98304, I8S_SMEM = 61440, I8_SMEM = 73728;
    cudaFuncSetAttribute(k_qkv_i8,    cudaFuncAttributeMaxDynamicSharedMemorySize, I8Q_SMEM);
    cudaFuncSetAttribute(k_scores_i8, cudaFuncAttributeMaxDynamicSharedMemorySize, I8S_SMEM);
    cudaFuncSetAttribute(k_out_i8,    cudaFuncAttributeMaxDynamicSharedMemorySize, I8Q_SMEM);
    cudaFuncSetAttribute(k_av_i8,     cudaFuncAttributeMaxDynamicSharedMemorySize, I8_SMEM);
    cudaFuncSetAttribute(k_aav_i8,    cudaFuncAttributeMaxDynamicSharedMemorySize, I8_SMEM);

    int8_t *xih, *xil, *wih, *wil, *oih, *oil, *woih, *woil;
    float *xs, *ws, *os, *wos, *gO;
    unsigned *vtm, *avtm;
    cudaGetSymbolAddress((void**)&xih,  g_xih);  cudaGetSymbolAddress((void**)&xil,  g_xil);
    cudaGetSymbolAddress((void**)&xs,   g_xs);
    cudaGetSymbolAddress((void**)&wih,  g_wih);  cudaGetSymbolAddress((void**)&wil,  g_wil);
    cudaGetSymbolAddress((void**)&ws,   g_ws);
    cudaGetSymbolAddress((void**)&oih,  g_Oih);  cudaGetSymbolAddress((void**)&oil,  g_Oil);
    cudaGetSymbolAddress((void**)&os,   g_Os);
    cudaGetSymbolAddress((void**)&woih, g_woih); cudaGetSymbolAddress((void**)&woil, g_woil);
    cudaGetSymbolAddress((void**)&wos,  g_wos);
    cudaGetSymbolAddress((void**)&gO,   g_O);
    cudaGetSymbolAddress((void**)&vtm,  g_vTmax); cudaGetSymbolAddress((void**)&avtm, g_AvTmax);

    k_quant<<<NB * NN, 256>>>(x, DIMC, xih, xil, xs);
    k_quant<<<3 * DIMC, 256>>>(qkv_w, DIMC, wih, wil, ws);
    k_quant<<<DIMC, 256>>>(Wout, DIMC, woih, woil, wos);
    k_qkv_i8<<<dim3(LDQKV / 128, (NB * NN) / 128), 512, I8Q_SMEM>>>();
    k_tqmax<<<dim3(8, NZ), 256>>>(0, vtm);
    k_tqq<<<dim3(8, NZ), 256>>>(0, vtm);
    k_scores_i8<<<dim3(NN / 128, NZ), 512, I8S_SMEM>>>();
    k_mix<<<NB * NN, 1024>>>(Lw, Lb, Ww, Wb);
    k_av_i8<<<dim3(1, NN / 128, NZ), 256, I8_SMEM>>>();
    k_tqmax<<<dim3(8, NZ), 256>>>(1, avtm);
    k_tqq<<<dim3(8, NZ), 256>>>(1, avtm);
    k_aav_i8<<<dim3(1, NN / 128, NZ), 256, I8_SMEM>>>(lamb);
    k_quant<<<NB * NN, 256>>>(gO, DIMC, oih, oil, os);
    k_out_i8<<<dim3(DIMC / 128, (NB * NN) / 128), 512, I8Q_SMEM>>>(bout, out);
}

// round 16
// speedup vs baseline: 1.1480x; 1.1480x over previous
#include <cuda_runtime.h>
#include <cuda_fp16.h>
#include <stdint.h>

#define HEADS 12
#define HD 64
#define DIMC 768
#define NB 4
#define NN 1024
#define LDQKV (3 * DIMC)
#define ATT_SCALE 0.125f
#define NZ (NB * HEADS)

// ---------------- global scratch ----------------
__device__ int8_t g_xih[(size_t)NB * NN * DIMC], g_xil[(size_t)NB * NN * DIMC];
__device__ float  g_xs[NB * NN];
__device__ int8_t g_wih[(size_t)3 * DIMC * DIMC], g_wil[(size_t)3 * DIMC * DIMC];
__device__ float  g_ws[3 * DIMC];
__device__ float  g_qkvf[(size_t)NB * NN * LDQKV];      // only V region used now
__device__ int8_t g_qih[(size_t)NZ * NN * HD], g_qil[(size_t)NZ * NN * HD];
__device__ float  g_qs[NZ * NN];
__device__ int8_t g_kih[(size_t)NZ * NN * HD], g_kil[(size_t)NZ * NN * HD];
__device__ float  g_ks[NZ * NN];
__device__ __half g_Sh[(size_t)NZ * NN * NN];           // fp16 scores
__device__ int8_t g_Aih[(size_t)NZ * NN * NN], g_Ail[(size_t)NZ * NN * NN];
__device__ float  g_As[NZ * NN];
__device__ int8_t g_vTih[(size_t)NZ * HD * NN], g_vTil[(size_t)NZ * HD * NN];
__device__ float  g_vTs[NZ * HD];
__device__ unsigned g_vTmax[NZ * HD];
__device__ float  g_Av[(size_t)NZ * NN * HD];
__device__ int8_t g_AvTih[(size_t)NZ * HD * NN], g_AvTil[(size_t)NZ * HD * NN];
__device__ float  g_AvTs[NZ * HD];
__device__ unsigned g_AvTmax[NZ * HD];
__device__ float  g_O[(size_t)NB * NN * DIMC];
__device__ int8_t g_Oih[(size_t)NB * NN * DIMC], g_Oil[(size_t)NB * NN * DIMC];
__device__ float  g_Os[NB * NN];
__device__ int8_t g_woih[(size_t)DIMC * DIMC], g_woil[(size_t)DIMC * DIMC];
__device__ float  g_wos[DIMC];

// ---------------- helpers ----------------
__device__ __forceinline__ void imma16832(int *c, const uint32_t *a, const uint32_t *b) {
    asm volatile(
        "mma.sync.aligned.m16n8k32.row.col.s32.s8.s8.s32 "
        "{%0,%1,%2,%3},{%4,%5,%6,%7},{%8,%9},{%0,%1,%2,%3};"
        : "+r"(c[0]), "+r"(c[1]), "+r"(c[2]), "+r"(c[3])
        : "r"(a[0]), "r"(a[1]), "r"(a[2]), "r"(a[3]), "r"(b[0]), "r"(b[1]));
}
__device__ __forceinline__ void ldm_x4(uint32_t (&r)[4], uint32_t a) {
    asm volatile("ldmatrix.sync.aligned.m8n8.x4.shared.b16 {%0,%1,%2,%3}, [%4];"
                 : "=r"(r[0]), "=r"(r[1]), "=r"(r[2]), "=r"(r[3]) : "r"(a));
}
__device__ __forceinline__ void ldm_x2(uint32_t (&r)[2], uint32_t a) {
    asm volatile("ldmatrix.sync.aligned.m8n8.x2.shared.b16 {%0,%1}, [%2];"
                 : "=r"(r[0]), "=r"(r[1]) : "r"(a));
}
__device__ __forceinline__ void cpa16(uint32_t s, const void *g) {
    asm volatile("cp.async.cg.shared.global [%0], [%1], 16;" :: "r"(s), "l"(g));
}
__device__ __forceinline__ void cpa_commit() { asm volatile("cp.async.commit_group;"); }

// ================= int8 NT engine core, BM=128 x BN=128, BK=32, 512 thr =================
template <int NSTAGE>
__device__ __forceinline__ void gemm_i8_128(
    const int8_t* Ah_, const int8_t* Al_, int lda,
    const int8_t* Bh_, const int8_t* Bl_, int ldb,
    int K, int (&hh)[2][4][4], int (&cx)[2][4][4])
{
    extern __shared__ __align__(16) int8_t smi[];
    const uint32_t sb = (uint32_t)__cvta_generic_to_shared(smi);
    const int t = threadIdx.x, lane = t & 31, wid = t >> 5;
    const int wm = wid >> 2, wn = wid & 3;

    const int lrow = (t >> 1) & 127, lseg = t & 1, lps = t >> 8;
    const int8_t* pA = (lps ? Al_ : Ah_) + (size_t)lrow * lda + lseg * 16;
    const int8_t* pB = (lps ? Bl_ : Bh_) + (size_t)lrow * ldb + lseg * 16;
    const uint32_t aoff = (uint32_t)(lps * 6144 + lrow * 48 + lseg * 16);
    const uint32_t boff = 12288u + (uint32_t)(lps * 6144 + lrow * 48 + lseg * 16);

    const int nst = K >> 5;
    auto issue = [&](int i) {
        const uint32_t s0 = sb + (uint32_t)(i & (NSTAGE - 1)) * 24576;
        cpa16(s0 + aoff, pA + i * 32);
        cpa16(s0 + boff, pB + i * 32);
        cpa_commit();
    };

    issue(0);
    if (nst > 1) issue(1);
    if (NSTAGE > 2 && nst > 2) issue(2);

    for (int i = 0; i < nst; i++) {
        if (NSTAGE > 2 && i + 3 < nst) {
            issue(i + 3);
            asm volatile("cp.async.wait_group 3;");
        } else {
            const int rem = nst - 1 - i;
            if (rem >= 2)      asm volatile("cp.async.wait_group 2;");
            else if (rem == 1) asm volatile("cp.async.wait_group 1;");
            else               asm volatile("cp.async.wait_group 0;");
        }
        __syncthreads();
        const uint32_t sA = sb + (uint32_t)(i & (NSTAGE - 1)) * 24576;
        const uint32_t sB = sA + 12288;
        uint32_t ah[2][4], al[2][4];
#pragma unroll
        for (int mf = 0; mf < 2; mf++) {
            const int m0 = wm * 32 + mf * 16;
            const uint32_t ad = sA + (uint32_t)((m0 + (lane & 15)) * 48) + ((lane >> 4) & 1) * 16;
            ldm_x4(ah[mf], ad);
            ldm_x4(al[mf], ad + 6144);
        }
#pragma unroll
        for (int nf = 0; nf < 4; nf++) {
            const int n0 = wn * 32 + nf * 8;
            const uint32_t bd = sB + (uint32_t)((n0 + (lane & 7)) * 48) + ((lane >> 3) & 1) * 16;
            uint32_t bh[2], bl[2];
            ldm_x2(bh, bd);
            ldm_x2(bl, bd + 6144);
#pragma unroll
            for (int mf = 0; mf < 2; mf++) {
                imma16832(hh[mf][nf], ah[mf], bh);
                imma16832(cx[mf][nf], ah[mf], bl);
                imma16832(cx[mf][nf], al[mf], bh);
            }
        }
        __syncthreads();
    }
}

// ================= int8 NT engine, BN=64: BM=128, BK=32, 4-stage, 256 thr =================
__device__ __forceinline__ void gemm_i8_64(
    const int8_t* Agh, const int8_t* Agl,
    const int8_t* Bgh, const int8_t* Bgl,
    int K, int (&hh)[2][4][4], int (&cx)[2][4][4])
{
    extern __shared__ __align__(16) int8_t smi[];
    const uint32_t sb = (uint32_t)__cvta_generic_to_shared(smi);
    const int t = threadIdx.x, lane = t & 31, wid = t >> 5;
    const int wm = wid >> 1, wn = wid & 1;

    const int arow = t >> 1, aseg = t & 1;
    const int brow = t & 63, bseg = (t >> 6) & 1, bpl = (t >> 7) & 1;
    const int8_t* pAh = Agh + (size_t)arow * K + aseg * 16;
    const int8_t* pAl = Agl + (size_t)arow * K + aseg * 16;
    const int8_t* pB  = (bpl ? Bgl : Bgh) + (size_t)brow * K + bseg * 16;
    const uint32_t aoff = (uint32_t)(arow * 48 + aseg * 16);
    const uint32_t boff = 12288u + (uint32_t)(bpl * 3072 + brow * 48 + bseg * 16);

    const int nst = K >> 5;
    auto issue = [&](int i) {
        const uint32_t s0 = sb + (uint32_t)(i & 3) * 18432;
        const int k0 = i * 32;
        cpa16(s0 + aoff,        pAh + k0);
        cpa16(s0 + 6144 + aoff, pAl + k0);
        cpa16(s0 + boff,        pB + k0);
        cpa_commit();
    };

    issue(0); issue(1); issue(2);

    for (int i = 0; i < nst; i++) {
        if (i + 3 < nst) {
            issue(i + 3);
            asm volatile("cp.async.wait_group 3;");
        } else {
            const int rem = nst - 1 - i;
            if (rem == 2)      asm volatile("cp.async.wait_group 2;");
            else if (rem == 1) asm volatile("cp.async.wait_group 1;");
            else               asm volatile("cp.async.wait_group 0;");
        }
        __syncthreads();
        const uint32_t sA = sb + (uint32_t)(i & 3) * 18432;
        const uint32_t sB = sA + 12288;
        uint32_t ah[2][4], al[2][4];
#pragma unroll
        for (int mf = 0; mf < 2; mf++) {
            const int m0 = wm * 32 + mf * 16;
            const uint32_t ad = sA + (uint32_t)((m0 + (lane & 15)) * 48) + ((lane >> 4) & 1) * 16;
            ldm_x4(ah[mf], ad);
            ldm_x4(al[mf], ad + 6144);
        }
#pragma unroll
        for (int nf = 0; nf < 4; nf++) {
            const int n0 = wn * 32 + nf * 8;
            const uint32_t bd = sB + (uint32_t)((n0 + (lane & 7)) * 48) + ((lane >> 3) & 1) * 16;
            uint32_t bh[2], bl[2];
            ldm_x2(bh, bd);
            ldm_x2(bl, bd + 3072);
#pragma unroll
            for (int mf = 0; mf < 2; mf++) {
                imma16832(hh[mf][nf], ah[mf], bh);
                imma16832(cx[mf][nf], ah[mf], bl);
                imma16832(cx[mf][nf], al[mf], bh);
            }
        }
        __syncthreads();
    }
}

// ---------------- row quantization ----------------
__global__ void __launch_bounds__(256) k_quant(const float* __restrict__ s, int K,
                                               int8_t* __restrict__ dh,
                                               int8_t* __restrict__ dl,
                                               float* __restrict__ sc)
{
    const int row = blockIdx.x;
    const float* p = s + (size_t)row * K;
    __shared__ float red[8];
    float m = 0.f;
    for (int i = threadIdx.x; i < K; i += 256) m = fmaxf(m, fabsf(p[i]));
#pragma unroll
    for (int o = 16; o; o >>= 1) m = fmaxf(m, __shfl_xor_sync(0xffffffffu, m, o));
    if ((threadIdx.x & 31) == 0) red[threadIdx.x >> 5] = m;
    __syncthreads();
    if (threadIdx.x == 0) {
        float v = red[0];
#pragma unroll
        for (int w = 1; w < 8; w++) v = fmaxf(v, red[w]);
        red[0] = v;
        sc[row] = v * (1.f / 16256.f);
    }
    __syncthreads();
    const float mx = red[0];
    const float inv = mx > 0.f ? 16256.f / mx : 0.f;
    for (int i = threadIdx.x; i < K; i += 256) {
        float q = p[i] * inv;
        float hf = rintf(q * (1.f / 128.f));
        float lf = rintf(q - 128.f * hf);
        dh[(size_t)row * K + i] = (int8_t)hf;
        dl[(size_t)row * K + i] = (int8_t)lf;
    }
}

// ---------------- transpose-quant of V / Av (two-phase) ----------------
__device__ __forceinline__ float tq_read(int mode, int z, int b, int h, int m, int d) {
    if (mode == 0)
        return g_qkvf[((size_t)b * NN + m) * LDQKV + 2 * DIMC + h * HD + d];
    return g_Av[((size_t)z * NN + m) * HD + d];
}

__global__ void __launch_bounds__(256) k_tqmax(int mode, unsigned* __restrict__ gmax)
{
    const int z = blockIdx.y, b = z / HEADS, h = z % HEADS;
    const int mt0 = blockIdx.x * 128;
    __shared__ float red4[4][64];
    const int t = threadIdx.x, d = t & 63, mg = t >> 6;
    float mx = 0.f;
    for (int m = mt0 + mg; m < mt0 + 128; m += 4)
        mx = fmaxf(mx, fabsf(tq_read(mode, z, b, h, m, d)));
    red4[mg][d] = mx;
    __syncthreads();
    if (t < 64) {
        float m2 = fmaxf(fmaxf(red4[0][t], red4[1][t]), fmaxf(red4[2][t], red4[3][t]));
        atomicMax(&gmax[z * HD + t], __float_as_uint(m2));
    }
}

__global__ void __launch_bounds__(256) k_tqq(int mode, const unsigned* __restrict__ gmax)
{
    const int z = blockIdx.y, b = z / HEADS, h = z % HEADS;
    const int mt0 = blockIdx.x * 128;
    __shared__ float sinv[64];
    __shared__ float tile[64][65];
    const int t = threadIdx.x, d = t & 63, mg = t >> 6;

    if (t < 64) {
        float m2 = __uint_as_float(gmax[z * HD + t]);
        sinv[t] = m2 > 0.f ? 16256.f / m2 : 0.f;
        if (blockIdx.x == 0)
            (mode ? g_AvTs : g_vTs)[z * HD + t] = m2 * (1.f / 16256.f);
    }
    __syncthreads();

    int8_t* oh = mode ? g_AvTih : g_vTih;
    int8_t* ol = mode ? g_AvTil : g_vTil;
    const int dd = t >> 2, seg = t & 3;
    for (int mt = mt0; mt < mt0 + 128; mt += 64) {
#pragma unroll 4
        for (int k = 0; k < 16; k++) {
            const int ml = mg + 4 * k;
            tile[ml][d] = tq_read(mode, z, b, h, mt + ml, d);
        }
        __syncthreads();
        __align__(16) int8_t hb[16], lb[16];
        const float inv = sinv[dd];
#pragma unroll
        for (int j = 0; j < 16; j++) {
            float q = tile[seg * 16 + j][dd] * inv;
            float hf = rintf(q * (1.f / 128.f));
            float lf = rintf(q - 128.f * hf);
            hb[j] = (int8_t)hf; lb[j] = (int8_t)lf;
        }
        const size_t off = ((size_t)z * HD + dd) * NN + mt + seg * 16;
        *(int4*)&oh[off] = *(const int4*)hb;
        *(int4*)&ol[off] = *(const int4*)lb;
        __syncthreads();
    }
}

// ================= qkv = x @ qkv_w^T; q/k quantized in-epilogue, V -> fp32 =================
__global__ void __launch_bounds__(512, 1) k_qkv_i8()
{
    __shared__ int   smax_i[128][2];
    __shared__ float sminv[128][2];
    const int row0 = blockIdx.y * 128, col0 = blockIdx.x * 128;
    int hh[2][4][4] = {}, cx[2][4][4] = {};
    gemm_i8_128<4>(g_xih + (size_t)row0 * DIMC, g_xil + (size_t)row0 * DIMC, DIMC,
                   g_wih + (size_t)col0 * DIMC, g_wil + (size_t)col0 * DIMC, DIMC,
                   DIMC, hh, cx);
    const int t = threadIdx.x;
    const int lane = t & 31, wid = t >> 5;
    const int wm = wid >> 2, wn = wid & 3, g = lane >> 2, tig = lane & 3;
    const int which = (col0 < DIMC) ? 0 : ((col0 < 2 * DIMC) ? 1 : 2);

    if (which == 2) {
#pragma unroll
        for (int mf = 0; mf < 2; mf++) {
            const int row = row0 + wm * 32 + mf * 16 + g;
            const float sr0 = g_xs[row], sr1 = g_xs[row + 8];
#pragma unroll
            for (int nf = 0; nf < 4; nf++) {
                const int col = col0 + wn * 32 + nf * 8 + tig * 2;
                const float sc0 = g_ws[col], sc1 = g_ws[col + 1];
                *(float2*)&g_qkvf[(size_t)row * LDQKV + col] = make_float2(
                    sr0 * sc0 * (16384.f * (float)hh[mf][nf][0] + 128.f * (float)cx[mf][nf][0]),
                    sr0 * sc1 * (16384.f * (float)hh[mf][nf][1] + 128.f * (float)cx[mf][nf][1]));
                *(float2*)&g_qkvf[(size_t)(row + 8) * LDQKV + col] = make_float2(
                    sr1 * sc0 * (16384.f * (float)hh[mf][nf][2] + 128.f * (float)cx[mf][nf][2]),
                    sr1 * sc1 * (16384.f * (float)hh[mf][nf][3] + 128.f * (float)cx[mf][nf][3]));
            }
        }
        return;
    }

    const float qsc = which ? 1.f : ATT_SCALE;
    const int half = wn >> 1;
    const int dbase = (wn & 1) * 32;

    if (t < 256) { smax_i[t >> 1][t & 1] = 0; }
    __syncthreads();

#pragma unroll
    for (int mf = 0; mf < 2; mf++) {
        const int rloc = wm * 32 + mf * 16 + g;
        const float sr0 = g_xs[row0 + rloc] * qsc, sr1 = g_xs[row0 + rloc + 8] * qsc;
        float m0 = 0.f, m1 = 0.f;
#pragma unroll
        for (int nf = 0; nf < 4; nf++) {
            const int col = col0 + wn * 32 + nf * 8 + tig * 2;
            const float sc0 = g_ws[col], sc1 = g_ws[col + 1];
            m0 = fmaxf(m0, fabsf(sr0 * sc0 * (16384.f * (float)hh[mf][nf][0] + 128.f * (float)cx[mf][nf][0])));
            m0 = fmaxf(m0, fabsf(sr0 * sc1 * (16384.f * (float)hh[mf][nf][1] + 128.f * (float)cx[mf][nf][1])));
            m1 = fmaxf(m1, fabsf(sr1 * sc0 * (16384.f * (float)hh[mf][nf][2] + 128.f * (float)cx[mf][nf][2])));
            m1 = fmaxf(m1, fabsf(sr1 * sc1 * (16384.f * (float)hh[mf][nf][3] + 128.f * (float)cx[mf][nf][3])));
        }
        atomicMax(&smax_i[rloc][half],     __float_as_int(m0));
        atomicMax(&smax_i[rloc + 8][half], __float_as_int(m1));
    }
    __syncthreads();

    const int head2 = (col0 - which * DIMC) >> 6;
    if (t < 256) {
        const int r = t >> 1, hf = t & 1;
        const float mx = __int_as_float(smax_i[r][hf]);
        const int grow = row0 + r, b = grow >> 10, n = grow & 1023;
        const int z = b * HEADS + head2 + hf;
        (which ? g_ks : g_qs)[z * NN + n] = mx * (1.f / 16256.f);
        sminv[r][hf] = mx > 0.f ? 16256.f / mx : 0.f;
    }
    __syncthreads();

    int8_t* dh = which ? g_kih : g_qih;
    int8_t* dl = which ? g_kil : g_qil;
#pragma unroll
    for (int mf = 0; mf < 2; mf++) {
        const int rloc = wm * 32 + mf * 16 + g;
        const float sr0 = g_xs[row0 + rloc] * qsc, sr1 = g_xs[row0 + rloc + 8] * qsc;
        const float inv0 = sminv[rloc][half], inv1 = sminv[rloc + 8][half];
        const int grow0 = row0 + rloc;
        const int b0 = grow0 >> 10, n0 = grow0 & 1023;
        const int z = b0 * HEADS + head2 + half;
        const size_t base0 = ((size_t)z * NN + n0) * HD;
        const size_t base1 = ((size_t)z * NN + n0 + 8) * HD;
#pragma unroll
        for (int nf = 0; nf < 4; nf++) {
            const int col = col0 + wn * 32 + nf * 8 + tig * 2;
            const int d = dbase + nf * 8 + tig * 2;
            const float sc0 = g_ws[col], sc1 = g_ws[col + 1];
            const float v00 = sr0 * sc0 * (16384.f * (float)hh[mf][nf][0] + 128.f * (float)cx[mf][nf][0]);
            const float v01 = sr0 * sc1 * (16384.f * (float)hh[mf][nf][1] + 128.f * (float)cx[mf][nf][1]);
            const float v10 = sr1 * sc0 * (16384.f * (float)hh[mf][nf][2] + 128.f * (float)cx[mf][nf][2]);
            const float v11 = sr1 * sc1 * (16384.f * (float)hh[mf][nf][3] + 128.f * (float)cx[mf][nf][3]);
            float q0 = v00 * inv0, q1 = v01 * inv0, q2 = v10 * inv1, q3 = v11 * inv1;
            float h0 = rintf(q0 * (1.f / 128.f)), h1 = rintf(q1 * (1.f / 128.f));
            float h2 = rintf(q2 * (1.f / 128.f)), h3 = rintf(q3 * (1.f / 128.f));
            *(char2*)&dh[base0 + d] = make_char2((signed char)h0, (signed char)h1);
            *(char2*)&dl[base0 + d] = make_char2((signed char)rintf(q0 - 128.f * h0),
                                                 (signed char)rintf(q1 - 128.f * h1));
            *(char2*)&dh[base1 + d] = make_char2((signed char)h2, (signed char)h3);
            *(char2*)&dl[base1 + d] = make_char2((signed char)rintf(q2 - 128.f * h2),
                                                 (signed char)rintf(q3 - 128.f * h3));
        }
    }
}

// ================= scores: persistent-q, fp16 S output =================
__global__ void __launch_bounds__(512, 1) k_scores_i8()
{
    extern __shared__ __align__(16) int8_t smi[];
    const uint32_t sb = (uint32_t)__cvta_generic_to_shared(smi);
    const int t = threadIdx.x, lane = t & 31, wid = t >> 5;
    const int wm = wid >> 2, wn = wid & 3;
    const int z = blockIdx.y;
    const int row0 = blockIdx.x * 128;

    const int qrow = t >> 2, qseg = t & 3;
    {
        const size_t src = ((size_t)z * NN + row0 + qrow) * HD + qseg * 16;
        const uint32_t d = sb + (uint32_t)(qrow * 80 + qseg * 16);
        cpa16(d,         g_qih + src);
        cpa16(d + 10240, g_qil + src);
    }
    cpa_commit();
    auto kissue = [&](int ct) {
        const size_t src = ((size_t)z * NN + ct * 128 + qrow) * HD + qseg * 16;
        const uint32_t d = sb + 20480 + (uint32_t)((ct & 1) * 20480 + qrow * 80 + qseg * 16);
        cpa16(d,         g_kih + src);
        cpa16(d + 10240, g_kil + src);
        cpa_commit();
    };
    kissue(0);

    asm volatile("cp.async.wait_group 1;");
    __syncthreads();
    uint32_t qah[2][2][4], qal[2][2][4];
#pragma unroll
    for (int s2 = 0; s2 < 2; s2++)
#pragma unroll
        for (int mf = 0; mf < 2; mf++) {
            const int m0 = wm * 32 + mf * 16;
            const uint32_t ad = sb + (uint32_t)((m0 + (lane & 15)) * 80) + s2 * 32 + ((lane >> 4) & 1) * 16;
            ldm_x4(qah[s2][mf], ad);
            ldm_x4(qal[s2][mf], ad + 10240);
        }

    const float* sq = g_qs + (size_t)z * NN;
    const float* sk = g_ks + (size_t)z * NN;
    __half* S = g_Sh + (size_t)z * NN * NN;
    const int g = lane >> 2, tig = lane & 3;

    for (int ct = 0; ct < 8; ct++) {
        if (ct + 1 < 8) { kissue(ct + 1); asm volatile("cp.async.wait_group 1;"); }
        else asm volatile("cp.async.wait_group 0;");
        __syncthreads();
        int hh[2][4][4] = {}, cx[2][4][4] = {};
        const uint32_t sK = sb + 20480 + (uint32_t)((ct & 1) * 20480);
#pragma unroll
        for (int s2 = 0; s2 < 2; s2++) {
#pragma unroll
            for (int nf = 0; nf < 4; nf++) {
                const int n0 = wn * 32 + nf * 8;
                const uint32_t bd = sK + (uint32_t)((n0 + (lane & 7)) * 80) + s2 * 32 + ((lane >> 3) & 1) * 16;
                uint32_t bh[2], bl[2];
                ldm_x2(bh, bd);
                ldm_x2(bl, bd + 10240);
#pragma unroll
                for (int mf = 0; mf < 2; mf++) {
                    imma16832(hh[mf][nf], qah[s2][mf], bh);
                    imma16832(cx[mf][nf], qah[s2][mf], bl);
                    imma16832(cx[mf][nf], qal[s2][mf], bh);
                }
            }
        }
        __syncthreads();
        const int col0 = ct * 128;
#pragma unroll
        for (int mf = 0; mf < 2; mf++) {
            const int row = row0 + wm * 32 + mf * 16 + g;
            const float sr0 = sq[row], sr1 = sq[row + 8];
#pragma unroll
            for (int nf = 0; nf < 4; nf++) {
                const int col = col0 + wn * 32 + nf * 8 + tig * 2;
                const float sc0 = sk[col], sc1 = sk[col + 1];
                *(__half2*)&S[(size_t)row * NN + col] = __floats2half2_rn(
                    sr0 * sc0 * (16384.f * (float)hh[mf][nf][0] + 128.f * (float)cx[mf][nf][0]),
                    sr0 * sc1 * (16384.f * (float)hh[mf][nf][1] + 128.f * (float)cx[mf][nf][1]));
                *(__half2*)&S[(size_t)(row + 8) * NN + col] = __floats2half2_rn(
                    sr1 * sc0 * (16384.f * (float)hh[mf][nf][2] + 128.f * (float)cx[mf][nf][2]),
                    sr1 * sc1 * (16384.f * (float)hh[mf][nf][3] + 128.f * (float)cx[mf][nf][3]));
            }
        }
    }
}

// ================= out = O @ Wout^T + bias =================
__global__ void __launch_bounds__(512, 1) k_out_i8(const float* __restrict__ bias,
                                                   float* __restrict__ out)
{
    const int row0 = blockIdx.y * 128, col0 = blockIdx.x * 128;
    int hh[2][4][4] = {}, cx[2][4][4] = {};
    gemm_i8_128<4>(g_Oih + (size_t)row0 * DIMC, g_Oil + (size_t)row0 * DIMC, DIMC,
                   g_woih + (size_t)col0 * DIMC, g_woil + (size_t)col0 * DIMC, DIMC,
                   DIMC, hh, cx);
    const int lane = threadIdx.x & 31, wid = threadIdx.x >> 5;
    const int wm = wid >> 2, wn = wid & 3, g = lane >> 2, tig = lane & 3;
#pragma unroll
    for (int mf = 0; mf < 2; mf++) {
        const int row = row0 + wm * 32 + mf * 16 + g;
        const float sr0 = g_Os[row], sr1 = g_Os[row + 8];
#pragma unroll
        for (int nf = 0; nf < 4; nf++) {
            const int col = col0 + wn * 32 + nf * 8 + tig * 2;
            const float sc0 = g_wos[col], sc1 = g_wos[col + 1];
            const float b0 = bias[col], b1 = bias[col + 1];
            *(float2*)&out[(size_t)row * DIMC + col] = make_float2(
                fmaf(sr0 * sc0, 16384.f * (float)hh[mf][nf][0] + 128.f * (float)cx[mf][nf][0], b0),
                fmaf(sr0 * sc1, 16384.f * (float)hh[mf][nf][1] + 128.f * (float)cx[mf][nf][1], b1));
            *(float2*)&out[(size_t)(row + 8) * DIMC + col] = make_float2(
                fmaf(sr1 * sc0, 16384.f * (float)hh[mf][nf][2] + 128.f * (float)cx[mf][nf][2], b0),
                fmaf(sr1 * sc1, 16384.f * (float)hh[mf][nf][3] + 128.f * (float)cx[mf][nf][3], b1));
        }
    }
}

// ---------------- int8 A@V and A@(A@V) ----------------
__global__ void __launch_bounds__(256, 2) k_av_i8()
{
    const int z = blockIdx.z;
    const int row0 = blockIdx.y * 128;
    int hh[2][4][4] = {}, cx[2][4][4] = {};
    gemm_i8_64(g_Aih + (size_t)z * NN * NN + (size_t)row0 * NN,
               g_Ail + (size_t)z * NN * NN + (size_t)row0 * NN,
               g_vTih + (size_t)z * HD * NN,
               g_vTil + (size_t)z * HD * NN, NN, hh, cx);
    const int lane = threadIdx.x & 31, wid = threadIdx.x >> 5;
    const int wm = wid >> 1, wn = wid & 1, g = lane >> 2, tig = lane & 3;
    float* Av = g_Av + (size_t)z * NN * HD;
#pragma unroll
    for (int mf = 0; mf < 2; mf++) {
        const int row = row0 + wm * 32 + mf * 16 + g;
        const float sr0 = g_As[(size_t)z * NN + row], sr1 = g_As[(size_t)z * NN + row + 8];
#pragma unroll
        for (int nf = 0; nf < 4; nf++) {
            const int col = wn * 32 + nf * 8 + tig * 2;
            const float sc0 = g_vTs[z * HD + col], sc1 = g_vTs[z * HD + col + 1];
            *(float2*)&Av[(size_t)row * HD + col] = make_float2(
                sr0 * sc0 * (16384.f * (float)hh[mf][nf][0] + 128.f * (float)cx[mf][nf][0]),
                sr0 * sc1 * (16384.f * (float)hh[mf][nf][1] + 128.f * (float)cx[mf][nf][1]));
            *(float2*)&Av[(size_t)(row + 8) * HD + col] = make_float2(
                sr1 * sc0 * (16384.f * (float)hh[mf][nf][2] + 128.f * (float)cx[mf][nf][2]),
                sr1 * sc1 * (16384.f * (float)hh[mf][nf][3] + 128.f * (float)cx[mf][nf][3]));
        }
    }
}

__global__ void __launch_bounds__(256, 2) k_aav_i8(const float* __restrict__ lamb)
{
    const int z = blockIdx.z, b = z / HEADS, h = z % HEADS;
    const int row0 = blockIdx.y * 128;
    int hh[2][4][4] = {}, cx[2][4][4] = {};
    gemm_i8_64(g_Aih + (size_t)z * NN * NN + (size_t)row0 * NN,
               g_Ail + (size_t)z * NN * NN + (size_t)row0 * NN,
               g_AvTih + (size_t)z * HD * NN,
               g_AvTil + (size_t)z * HD * NN, NN, hh, cx);
    const float lam = lamb[h];
    const float c1 = 1.f - 2.f * lam, c3 = 3.f * lam;
    const int lane = threadIdx.x & 31, wid = threadIdx.x >> 5;
    const int wm = wid >> 1, wn = wid & 1, g = lane >> 2, tig = lane & 3;
    const float* Av = g_Av + (size_t)z * NN * HD;
#pragma unroll
    for (int mf = 0; mf < 2; mf++) {
        const int row = row0 + wm * 32 + mf * 16 + g;
        const float sr0 = g_As[(size_t)z * NN + row], sr1 = g_As[(size_t)z * NN + row + 8];
#pragma unroll
        for (int nf = 0; nf < 4; nf++) {
            const int col = wn * 32 + nf * 8 + tig * 2;
            const float sc0 = g_AvTs[z * HD + col], sc1 = g_AvTs[z * HD + col + 1];
            const float r00 = sr0 * sc0 * (16384.f * (float)hh[mf][nf][0] + 128.f * (float)cx[mf][nf][0]);
            const float r01 = sr0 * sc1 * (16384.f * (float)hh[mf][nf][1] + 128.f * (float)cx[mf][nf][1]);
            const float r10 = sr1 * sc0 * (16384.f * (float)hh[mf][nf][2] + 128.f * (float)cx[mf][nf][2]);
            const float r11 = sr1 * sc1 * (16384.f * (float)hh[mf][nf][3] + 128.f * (float)cx[mf][nf][3]);
            float2 av0 = *(const float2*)&Av[(size_t)row * HD + col];
            float2 av1 = *(const float2*)&Av[(size_t)(row + 8) * HD + col];
            const size_t oi0 = ((size_t)b * NN + row) * DIMC + h * HD + col;
            const size_t oi1 = ((size_t)b * NN + row + 8) * DIMC + h * HD + col;
            *(float2*)&g_O[oi0] = make_float2(fmaf(c3, r00, c1 * av0.x), fmaf(c3, r01, c1 * av0.y));
            *(float2*)&g_O[oi1] = make_float2(fmaf(c3, r10, c1 * av1.x), fmaf(c3, r11, c1 * av1.y));
        }
    }
}

// ---------------- register-resident L-mix -> softmax -> W-mix -> int8 A quant ----------------
// 512 threads, 2 columns per thread (half2 loads / char2 stores); 128-reg budget, no spills.
__global__ void __launch_bounds__(512) k_mix(const float* __restrict__ Lw,
                                             const float* __restrict__ Lb,
                                             const float* __restrict__ Ww,
                                             const float* __restrict__ Wb)
{
    __shared__ float sL[144], sW[144], sbl[12], sbw[12];
    __shared__ float red[12][16];
    __shared__ float gmax[12], ginv[12], sAinv[12];

    const int tid = threadIdx.x;
    const int b = blockIdx.x >> 10;
    const int n = blockIdx.x & 1023;

    if (tid < 144) { sL[tid] = Lw[tid]; sW[tid] = Ww[tid]; }
    if (tid < 12)  { sbl[tid] = Lb[tid]; sbw[tid] = Wb[tid]; }
    __syncthreads();

    const __half* Sbase = g_Sh + (size_t)b * HEADS * NN * NN + (size_t)n * NN;
    const int lane = tid & 31, wrp = tid >> 5;
    const int m = tid * 2;

    float2 s[12];
#pragma unroll
    for (int h = 0; h < 12; h++)
        s[h] = __half22float2(*(const __half2*)&Sbase[(size_t)h * NN * NN + m]);

    // L-mix + per-head max (overwrite s with mixed values a)
    float2 a[12];
#pragma unroll
    for (int g = 0; g < 12; g++) {
        float t0 = sbl[g], t1 = sbl[g];
#pragma unroll
        for (int h = 0; h < 12; h++) {
            t0 = fmaf(sL[g * 12 + h], s[h].x, t0);
            t1 = fmaf(sL[g * 12 + h], s[h].y, t1);
        }
        a[g] = make_float2(t0, t1);
    }
#pragma unroll
    for (int g = 0; g < 12; g++) {
        float v = fmaxf(a[g].x, a[g].y);
#pragma unroll
        for (int o = 16; o; o >>= 1) v = fmaxf(v, __shfl_xor_sync(0xffffffffu, v, o));
        if (lane == 0) red[g][wrp] = v;
    }
    __syncthreads();
    if (tid < 12) {
        float v = red[tid][0];
#pragma unroll
        for (int w = 1; w < 16; w++) v = fmaxf(v, red[tid][w]);
        gmax[tid] = v;
    }
    __syncthreads();

    // exp + sum (a becomes exp values)
#pragma unroll
    for (int g = 0; g < 12; g++) {
        a[g].x = __expf(a[g].x - gmax[g]);
        a[g].y = __expf(a[g].y - gmax[g]);
    }
#pragma unroll
    for (int g = 0; g < 12; g++) {
        float v = a[g].x + a[g].y;
#pragma unroll
        for (int o = 16; o; o >>= 1) v += __shfl_xor_sync(0xffffffffu, v, o);
        if (lane == 0) red[g][wrp] = v;
    }
    __syncthreads();
    if (tid < 12) {
        float v = red[tid][0];
#pragma unroll
        for (int w = 1; w < 16; w++) v += red[tid][w];
        ginv[tid] = 1.f / v;
    }
    __syncthreads();

    // normalize (s = probabilities) + W-mix (a = output) + per-head max|a|
#pragma unroll
    for (int h = 0; h < 12; h++) {
        s[h].x = a[h].x * ginv[h];
        s[h].y = a[h].y * ginv[h];
    }
#pragma unroll
    for (int g = 0; g < 12; g++) {
        float t0 = sbw[g], t1 = sbw[g];
#pragma unroll
        for (int h = 0; h < 12; h++) {
            t0 = fmaf(sW[g * 12 + h], s[h].x, t0);
            t1 = fmaf(sW[g * 12 + h], s[h].y, t1);
        }
        a[g] = make_float2(t0, t1);
    }
#pragma unroll
    for (int g = 0; g < 12; g++) {
        float v = fmaxf(fabsf(a[g].x), fabsf(a[g].y));
#pragma unroll
        for (int o = 16; o; o >>= 1) v = fmaxf(v, __shfl_xor_sync(0xffffffffu, v, o));
        if (lane == 0) red[g][wrp] = v;
    }
    __syncthreads();
    if (tid < 12) {
        float v = red[tid][0];
#pragma unroll
        for (int w = 1; w < 16; w++) v = fmaxf(v, red[tid][w]);
        g_As[((size_t)b * HEADS + tid) * NN + n] = v * (1.f / 16256.f);
        sAinv[tid] = v > 0.f ? 16256.f / v : 0.f;
    }
    __syncthreads();

    // quantize + vectorized store
    const size_t abase = (size_t)b * HEADS * NN * NN + (size_t)n * NN;
#pragma unroll
    for (int g = 0; g < 12; g++) {
        const float inv = sAinv[g];
        float q0 = a[g].x * inv, q1 = a[g].y * inv;
        float h0 = rintf(q0 * (1.f / 128.f)), h1 = rintf(q1 * (1.f / 128.f));
        float l0 = rintf(q0 - 128.f * h0),    l1 = rintf(q1 - 128.f * h1);
        const size_t o = abase + (size_t)g * NN * NN + m;
        *(char2*)&g_Aih[o] = make_char2((signed char)h0, (signed char)h1);
        *(char2*)&g_Ail[o] = make_char2((signed char)l0, (signed char)l1);
    }
}

// ---------------- launch ----------------
extern "C" void kernel_launch(void* const* d_in, const int* in_sizes, int n_in,
                              void* d_out, int out_size)
{
    (void)in_sizes; (void)n_in; (void)out_size;
    const float* x      = (const float*)d_in[0];
    const float* qkv_w  = (const float*)d_in[1];
    const float* Lw     = (const float*)d_in[2];
    const float* Lb     = (const float*)d_in[3];
    const float* Ww     = (const float*)d_in[4];
    const float* Wb     = (const float*)d_in[5];
    const float* lamb   = (const float*)d_in[6];
    const float* Wout   = (const float*)d_in[7];
    const float* bout   = (const float*)d_in[8];
    float* out = (float*)d_out;

    const int I8Q_SMEM = 98304, I8S_SMEM = 61440, I8_SMEM = 73728;
    cudaFuncSetAttribute(k_qkv_i8,    cudaFuncAttributeMaxDynamicSharedMemorySize, I8Q_SMEM);
    cudaFuncSetAttribute(k_scores_i8, cudaFuncAttributeMaxDynamicSharedMemorySize, I8S_SMEM);
    cudaFuncSetAttribute(k_out_i8,    cudaFuncAttributeMaxDynamicSharedMemorySize, I8Q_SMEM);
    cudaFuncSetAttribute(k_av_i8,     cudaFuncAttributeMaxDynamicSharedMemorySize, I8_SMEM);
    cudaFuncSetAttribute(k_aav_i8,    cudaFuncAttributeMaxDynamicSharedMemorySize, I8_SMEM);

    int8_t *xih, *xil, *wih, *wil, *oih, *oil, *woih, *woil;
    float *xs, *ws, *os, *wos, *gO;
    unsigned *vtm, *avtm;
    cudaGetSymbolAddress((void**)&xih,  g_xih);  cudaGetSymbolAddress((void**)&xil,  g_xil);
    cudaGetSymbolAddress((void**)&xs,   g_xs);
    cudaGetSymbolAddress((void**)&wih,  g_wih);  cudaGetSymbolAddress((void**)&wil,  g_wil);
    cudaGetSymbolAddress((void**)&ws,   g_ws);
    cudaGetSymbolAddress((void**)&oih,  g_Oih);  cudaGetSymbolAddress((void**)&oil,  g_Oil);
    cudaGetSymbolAddress((void**)&os,   g_Os);
    cudaGetSymbolAddress((void**)&woih, g_woih); cudaGetSymbolAddress((void**)&woil, g_woil);
    cudaGetSymbolAddress((void**)&wos,  g_wos);
    cudaGetSymbolAddress((void**)&gO,   g_O);
    cudaGetSymbolAddress((void**)&vtm,  g_vTmax); cudaGetSymbolAddress((void**)&avtm, g_AvTmax);

    k_quant<<<NB * NN, 256>>>(x, DIMC, xih, xil, xs);
    k_quant<<<3 * DIMC, 256>>>(qkv_w, DIMC, wih, wil, ws);
    k_quant<<<DIMC, 256>>>(Wout, DIMC, woih, woil, wos);
    k_qkv_i8<<<dim3(LDQKV / 128, (NB * NN) / 128), 512, I8Q_SMEM>>>();
    k_tqmax<<<dim3(8, NZ), 256>>>(0, vtm);
    k_tqq<<<dim3(8, NZ), 256>>>(0, vtm);
    k_scores_i8<<<dim3(NN / 128, NZ), 512, I8S_SMEM>>>();
    k_mix<<<NB * NN, 512>>>(Lw, Lb, Ww, Wb);
    k_av_i8<<<dim3(1, NN / 128, NZ), 256, I8_SMEM>>>();
    k_tqmax<<<dim3(8, NZ), 256>>>(1, avtm);
    k_tqq<<<dim3(8, NZ), 256>>>(1, avtm);
    k_aav_i8<<<dim3(1, NN / 128, NZ), 256, I8_SMEM>>>(lamb);
    k_quant<<<NB * NN, 256>>>(gO, DIMC, oih, oil, os);
    k_out_i8<<<dim3(DIMC / 128, (NB * NN) / 128), 512, I8Q_SMEM>>>(bout, out);
}

// round 17
// speedup vs baseline: 1.1777x; 1.0258x over previous
#include <cuda_runtime.h>
#include <cuda_fp16.h>
#include <stdint.h>

#define HEADS 12
#define HD 64
#define DIMC 768
#define NB 4
#define NN 1024
#define LDQKV (3 * DIMC)
#define ATT_SCALE 0.125f
#define NZ (NB * HEADS)

// ---------------- global scratch ----------------
__device__ int8_t g_xih[(size_t)NB * NN * DIMC], g_xil[(size_t)NB * NN * DIMC];
__device__ float  g_xs[NB * NN];
__device__ int8_t g_wih[(size_t)3 * DIMC * DIMC], g_wil[(size_t)3 * DIMC * DIMC];
__device__ float  g_ws[3 * DIMC];
__device__ float  g_qkvf[(size_t)NB * NN * LDQKV];      // only V region used
__device__ int8_t g_qih[(size_t)NZ * NN * HD], g_qil[(size_t)NZ * NN * HD];
__device__ float  g_qs[NZ * NN];
__device__ int8_t g_kih[(size_t)NZ * NN * HD], g_kil[(size_t)NZ * NN * HD];
__device__ float  g_ks[NZ * NN];
__device__ __half g_Sh[(size_t)NZ * NN * NN];           // fp16 scores
__device__ int8_t g_Aih[(size_t)NZ * NN * NN], g_Ail[(size_t)NZ * NN * NN];
__device__ float  g_As[NZ * NN];
__device__ int8_t g_vTih[(size_t)NZ * HD * NN], g_vTil[(size_t)NZ * HD * NN];
__device__ float  g_vTs[NZ * HD];
__device__ unsigned g_vTmax[NZ * HD];    // zero-init; atomicMax idempotent across replays
__device__ float  g_Av[(size_t)NZ * NN * HD];
__device__ int8_t g_AvTih[(size_t)NZ * HD * NN], g_AvTil[(size_t)NZ * HD * NN];
__device__ float  g_AvTs[NZ * HD];
__device__ unsigned g_AvTmax[NZ * HD];
__device__ float  g_O[(size_t)NB * NN * DIMC];
__device__ int8_t g_Oih[(size_t)NB * NN * DIMC], g_Oil[(size_t)NB * NN * DIMC];
__device__ float  g_Os[NB * NN];
__device__ int8_t g_woih[(size_t)DIMC * DIMC], g_woil[(size_t)DIMC * DIMC];
__device__ float  g_wos[DIMC];

// ---------------- helpers ----------------
__device__ __forceinline__ void imma16832(int *c, const uint32_t *a, const uint32_t *b) {
    asm volatile(
        "mma.sync.aligned.m16n8k32.row.col.s32.s8.s8.s32 "
        "{%0,%1,%2,%3},{%4,%5,%6,%7},{%8,%9},{%0,%1,%2,%3};"
        : "+r"(c[0]), "+r"(c[1]), "+r"(c[2]), "+r"(c[3])
        : "r"(a[0]), "r"(a[1]), "r"(a[2]), "r"(a[3]), "r"(b[0]), "r"(b[1]));
}
__device__ __forceinline__ void ldm_x4(uint32_t (&r)[4], uint32_t a) {
    asm volatile("ldmatrix.sync.aligned.m8n8.x4.shared.b16 {%0,%1,%2,%3}, [%4];"
                 : "=r"(r[0]), "=r"(r[1]), "=r"(r[2]), "=r"(r[3]) : "r"(a));
}
__device__ __forceinline__ void ldm_x2(uint32_t (&r)[2], uint32_t a) {
    asm volatile("ldmatrix.sync.aligned.m8n8.x2.shared.b16 {%0,%1}, [%2];"
                 : "=r"(r[0]), "=r"(r[1]) : "r"(a));
}
__device__ __forceinline__ void cpa16(uint32_t s, const void *g) {
    asm volatile("cp.async.cg.shared.global [%0], [%1], 16;" :: "r"(s), "l"(g));
}
__device__ __forceinline__ void cpa_commit() { asm volatile("cp.async.commit_group;"); }

// ================= int8 NT engine core, BM=128 x BN=128, BK=32, 512 thr =================
template <int NSTAGE>
__device__ __forceinline__ void gemm_i8_128(
    const int8_t* Ah_, const int8_t* Al_, int lda,
    const int8_t* Bh_, const int8_t* Bl_, int ldb,
    int K, int (&hh)[2][4][4], int (&cx)[2][4][4])
{
    extern __shared__ __align__(16) int8_t smi[];
    const uint32_t sb = (uint32_t)__cvta_generic_to_shared(smi);
    const int t = threadIdx.x, lane = t & 31, wid = t >> 5;
    const int wm = wid >> 2, wn = wid & 3;

    const int lrow = (t >> 1) & 127, lseg = t & 1, lps = t >> 8;
    const int8_t* pA = (lps ? Al_ : Ah_) + (size_t)lrow * lda + lseg * 16;
    const int8_t* pB = (lps ? Bl_ : Bh_) + (size_t)lrow * ldb + lseg * 16;
    const uint32_t aoff = (uint32_t)(lps * 6144 + lrow * 48 + lseg * 16);
    const uint32_t boff = 12288u + (uint32_t)(lps * 6144 + lrow * 48 + lseg * 16);

    const int nst = K >> 5;
    auto issue = [&](int i) {
        const uint32_t s0 = sb + (uint32_t)(i & (NSTAGE - 1)) * 24576;
        cpa16(s0 + aoff, pA + i * 32);
        cpa16(s0 + boff, pB + i * 32);
        cpa_commit();
    };

    issue(0);
    if (nst > 1) issue(1);
    if (NSTAGE > 2 && nst > 2) issue(2);

    for (int i = 0; i < nst; i++) {
        if (NSTAGE > 2 && i + 3 < nst) {
            issue(i + 3);
            asm volatile("cp.async.wait_group 3;");
        } else {
            const int rem = nst - 1 - i;
            if (rem >= 2)      asm volatile("cp.async.wait_group 2;");
            else if (rem == 1) asm volatile("cp.async.wait_group 1;");
            else               asm volatile("cp.async.wait_group 0;");
        }
        __syncthreads();
        const uint32_t sA = sb + (uint32_t)(i & (NSTAGE - 1)) * 24576;
        const uint32_t sB = sA + 12288;
        uint32_t ah[2][4], al[2][4];
#pragma unroll
        for (int mf = 0; mf < 2; mf++) {
            const int m0 = wm * 32 + mf * 16;
            const uint32_t ad = sA + (uint32_t)((m0 + (lane & 15)) * 48) + ((lane >> 4) & 1) * 16;
            ldm_x4(ah[mf], ad);
            ldm_x4(al[mf], ad + 6144);
        }
#pragma unroll
        for (int nf = 0; nf < 4; nf++) {
            const int n0 = wn * 32 + nf * 8;
            const uint32_t bd = sB + (uint32_t)((n0 + (lane & 7)) * 48) + ((lane >> 3) & 1) * 16;
            uint32_t bh[2], bl[2];
            ldm_x2(bh, bd);
            ldm_x2(bl, bd + 6144);
#pragma unroll
            for (int mf = 0; mf < 2; mf++) {
                imma16832(hh[mf][nf], ah[mf], bh);
                imma16832(cx[mf][nf], ah[mf], bl);
                imma16832(cx[mf][nf], al[mf], bh);
            }
        }
        __syncthreads();
    }
}

// ================= int8 NT engine, BN=64: BM=128, BK=32, 4-stage, 256 thr =================
__device__ __forceinline__ void gemm_i8_64(
    const int8_t* Agh, const int8_t* Agl,
    const int8_t* Bgh, const int8_t* Bgl,
    int K, int (&hh)[2][4][4], int (&cx)[2][4][4])
{
    extern __shared__ __align__(16) int8_t smi[];
    const uint32_t sb = (uint32_t)__cvta_generic_to_shared(smi);
    const int t = threadIdx.x, lane = t & 31, wid = t >> 5;
    const int wm = wid >> 1, wn = wid & 1;

    const int arow = t >> 1, aseg = t & 1;
    const int brow = t & 63, bseg = (t >> 6) & 1, bpl = (t >> 7) & 1;
    const int8_t* pAh = Agh + (size_t)arow * K + aseg * 16;
    const int8_t* pAl = Agl + (size_t)arow * K + aseg * 16;
    const int8_t* pB  = (bpl ? Bgl : Bgh) + (size_t)brow * K + bseg * 16;
    const uint32_t aoff = (uint32_t)(arow * 48 + aseg * 16);
    const uint32_t boff = 12288u + (uint32_t)(bpl * 3072 + brow * 48 + bseg * 16);

    const int nst = K >> 5;
    auto issue = [&](int i) {
        const uint32_t s0 = sb + (uint32_t)(i & 3) * 18432;
        const int k0 = i * 32;
        cpa16(s0 + aoff,        pAh + k0);
        cpa16(s0 + 6144 + aoff, pAl + k0);
        cpa16(s0 + boff,        pB + k0);
        cpa_commit();
    };

    issue(0); issue(1); issue(2);

    for (int i = 0; i < nst; i++) {
        if (i + 3 < nst) {
            issue(i + 3);
            asm volatile("cp.async.wait_group 3;");
        } else {
            const int rem = nst - 1 - i;
            if (rem == 2)      asm volatile("cp.async.wait_group 2;");
            else if (rem == 1) asm volatile("cp.async.wait_group 1;");
            else               asm volatile("cp.async.wait_group 0;");
        }
        __syncthreads();
        const uint32_t sA = sb + (uint32_t)(i & 3) * 18432;
        const uint32_t sB = sA + 12288;
        uint32_t ah[2][4], al[2][4];
#pragma unroll
        for (int mf = 0; mf < 2; mf++) {
            const int m0 = wm * 32 + mf * 16;
            const uint32_t ad = sA + (uint32_t)((m0 + (lane & 15)) * 48) + ((lane >> 4) & 1) * 16;
            ldm_x4(ah[mf], ad);
            ldm_x4(al[mf], ad + 6144);
        }
#pragma unroll
        for (int nf = 0; nf < 4; nf++) {
            const int n0 = wn * 32 + nf * 8;
            const uint32_t bd = sB + (uint32_t)((n0 + (lane & 7)) * 48) + ((lane >> 3) & 1) * 16;
            uint32_t bh[2], bl[2];
            ldm_x2(bh, bd);
            ldm_x2(bl, bd + 3072);
#pragma unroll
            for (int mf = 0; mf < 2; mf++) {
                imma16832(hh[mf][nf], ah[mf], bh);
                imma16832(cx[mf][nf], ah[mf], bl);
                imma16832(cx[mf][nf], al[mf], bh);
            }
        }
        __syncthreads();
    }
}

// ---------------- merged row quantization for x / qkv_w / Wout (all K=DIMC) ----------------
__global__ void __launch_bounds__(256) k_quant_all(
    const float* __restrict__ x, const float* __restrict__ qkv_w, const float* __restrict__ wout)
{
    const float* src;
    int8_t *dh, *dl;
    float* sc;
    int row;
    if (blockIdx.x < NB * NN) {
        src = x; row = blockIdx.x; dh = g_xih; dl = g_xil; sc = g_xs;
    } else if (blockIdx.x < NB * NN + 3 * DIMC) {
        src = qkv_w; row = blockIdx.x - NB * NN; dh = g_wih; dl = g_wil; sc = g_ws;
    } else {
        src = wout; row = blockIdx.x - NB * NN - 3 * DIMC; dh = g_woih; dl = g_woil; sc = g_wos;
    }
    const float* p = src + (size_t)row * DIMC;
    __shared__ float red[8];
    float m = 0.f;
    for (int i = threadIdx.x; i < DIMC; i += 256) m = fmaxf(m, fabsf(p[i]));
#pragma unroll
    for (int o = 16; o; o >>= 1) m = fmaxf(m, __shfl_xor_sync(0xffffffffu, m, o));
    if ((threadIdx.x & 31) == 0) red[threadIdx.x >> 5] = m;
    __syncthreads();
    if (threadIdx.x == 0) {
        float v = red[0];
#pragma unroll
        for (int w = 1; w < 8; w++) v = fmaxf(v, red[w]);
        red[0] = v;
        sc[row] = v * (1.f / 16256.f);
    }
    __syncthreads();
    const float mx = red[0];
    const float inv = mx > 0.f ? 16256.f / mx : 0.f;
    for (int i = threadIdx.x; i < DIMC; i += 256) {
        float q = p[i] * inv;
        float hf = rintf(q * (1.f / 128.f));
        float lf = rintf(q - 128.f * hf);
        dh[(size_t)row * DIMC + i] = (int8_t)hf;
        dl[(size_t)row * DIMC + i] = (int8_t)lf;
    }
}

// ---------------- O row quantization (K=DIMC) ----------------
__global__ void __launch_bounds__(256) k_quant(const float* __restrict__ s, int K,
                                               int8_t* __restrict__ dh,
                                               int8_t* __restrict__ dl,
                                               float* __restrict__ sc)
{
    const int row = blockIdx.x;
    const float* p = s + (size_t)row * K;
    __shared__ float red[8];
    float m = 0.f;
    for (int i = threadIdx.x; i < K; i += 256) m = fmaxf(m, fabsf(p[i]));
#pragma unroll
    for (int o = 16; o; o >>= 1) m = fmaxf(m, __shfl_xor_sync(0xffffffffu, m, o));
    if ((threadIdx.x & 31) == 0) red[threadIdx.x >> 5] = m;
    __syncthreads();
    if (threadIdx.x == 0) {
        float v = red[0];
#pragma unroll
        for (int w = 1; w < 8; w++) v = fmaxf(v, red[w]);
        red[0] = v;
        sc[row] = v * (1.f / 16256.f);
    }
    __syncthreads();
    const float mx = red[0];
    const float inv = mx > 0.f ? 16256.f / mx : 0.f;
    for (int i = threadIdx.x; i < K; i += 256) {
        float q = p[i] * inv;
        float hf = rintf(q * (1.f / 128.f));
        float lf = rintf(q - 128.f * hf);
        dh[(size_t)row * K + i] = (int8_t)hf;
        dl[(size_t)row * K + i] = (int8_t)lf;
    }
}

// ---------------- transpose-quant (reads gmax produced by producer epilogues) ----------------
__device__ __forceinline__ float tq_read(int mode, int z, int b, int h, int m, int d) {
    if (mode == 0)
        return g_qkvf[((size_t)b * NN + m) * LDQKV + 2 * DIMC + h * HD + d];
    return g_Av[((size_t)z * NN + m) * HD + d];
}

__global__ void __launch_bounds__(256) k_tqq(int mode, const unsigned* __restrict__ gmax)
{
    const int z = blockIdx.y, b = z / HEADS, h = z % HEADS;
    const int mt0 = blockIdx.x * 128;
    __shared__ float sinv[64];
    __shared__ float tile[64][65];
    const int t = threadIdx.x, d = t & 63, mg = t >> 6;

    if (t < 64) {
        float m2 = __uint_as_float(gmax[z * HD + t]);
        sinv[t] = m2 > 0.f ? 16256.f / m2 : 0.f;
        if (blockIdx.x == 0)
            (mode ? g_AvTs : g_vTs)[z * HD + t] = m2 * (1.f / 16256.f);
    }
    __syncthreads();

    int8_t* oh = mode ? g_AvTih : g_vTih;
    int8_t* ol = mode ? g_AvTil : g_vTil;
    const int dd = t >> 2, seg = t & 3;
    for (int mt = mt0; mt < mt0 + 128; mt += 64) {
#pragma unroll 4
        for (int k = 0; k < 16; k++) {
            const int ml = mg + 4 * k;
            tile[ml][d] = tq_read(mode, z, b, h, mt + ml, d);
        }
        __syncthreads();
        __align__(16) int8_t hb[16], lb[16];
        const float inv = sinv[dd];
#pragma unroll
        for (int j = 0; j < 16; j++) {
            float q = tile[seg * 16 + j][dd] * inv;
            float hf = rintf(q * (1.f / 128.f));
            float lf = rintf(q - 128.f * hf);
            hb[j] = (int8_t)hf; lb[j] = (int8_t)lf;
        }
        const size_t off = ((size_t)z * HD + dd) * NN + mt + seg * 16;
        *(int4*)&oh[off] = *(const int4*)hb;
        *(int4*)&ol[off] = *(const int4*)lb;
        __syncthreads();
    }
}

// ================= qkv = x @ qkv_w^T; q/k quantized in-epilogue; V -> fp32 + fused col-max =================
__global__ void __launch_bounds__(512, 1) k_qkv_i8()
{
    __shared__ int   smax_i[128][2];
    __shared__ float sminv[128][2];
    const int row0 = blockIdx.y * 128, col0 = blockIdx.x * 128;
    int hh[2][4][4] = {}, cx[2][4][4] = {};
    gemm_i8_128<4>(g_xih + (size_t)row0 * DIMC, g_xil + (size_t)row0 * DIMC, DIMC,
                   g_wih + (size_t)col0 * DIMC, g_wil + (size_t)col0 * DIMC, DIMC,
                   DIMC, hh, cx);
    const int t = threadIdx.x;
    const int lane = t & 31, wid = t >> 5;
    const int wm = wid >> 2, wn = wid & 3, g = lane >> 2, tig = lane & 3;
    const int which = (col0 < DIMC) ? 0 : ((col0 < 2 * DIMC) ? 1 : 2);

    if (which == 2) {
        // V tiles: write fp32 + fused per-column |max| into g_vTmax
        __shared__ int scol[128];
        if (t < 128) scol[t] = 0;
        __syncthreads();
        const int b = row0 >> 10;                 // whole tile in one batch (128 | 1024)
        const int hbase = (col0 - 2 * DIMC) >> 6; // first head covered by this tile
#pragma unroll
        for (int mf = 0; mf < 2; mf++) {
            const int row = row0 + wm * 32 + mf * 16 + g;
            const float sr0 = g_xs[row], sr1 = g_xs[row + 8];
#pragma unroll
            for (int nf = 0; nf < 4; nf++) {
                const int col = col0 + wn * 32 + nf * 8 + tig * 2;
                const float sc0 = g_ws[col], sc1 = g_ws[col + 1];
                const float v00 = sr0 * sc0 * (16384.f * (float)hh[mf][nf][0] + 128.f * (float)cx[mf][nf][0]);
                const float v01 = sr0 * sc1 * (16384.f * (float)hh[mf][nf][1] + 128.f * (float)cx[mf][nf][1]);
                const float v10 = sr1 * sc0 * (16384.f * (float)hh[mf][nf][2] + 128.f * (float)cx[mf][nf][2]);
                const float v11 = sr1 * sc1 * (16384.f * (float)hh[mf][nf][3] + 128.f * (float)cx[mf][nf][3]);
                *(float2*)&g_qkvf[(size_t)row * LDQKV + col] = make_float2(v00, v01);
                *(float2*)&g_qkvf[(size_t)(row + 8) * LDQKV + col] = make_float2(v10, v11);
                const int cl = col - col0;
                atomicMax(&scol[cl],     __float_as_int(fmaxf(fabsf(v00), fabsf(v10))));
                atomicMax(&scol[cl + 1], __float_as_int(fmaxf(fabsf(v01), fabsf(v11))));
            }
        }
        __syncthreads();
        if (t < 128) {
            const int h = hbase + (t >> 6), d = t & 63;
            atomicMax(&g_vTmax[(b * HEADS + h) * HD + d], (unsigned)scol[t]);
        }
        return;
    }

    const float qsc = which ? 1.f : ATT_SCALE;
    const int half = wn >> 1;
    const int dbase = (wn & 1) * 32;

    if (t < 256) { smax_i[t >> 1][t & 1] = 0; }
    __syncthreads();

#pragma unroll
    for (int mf = 0; mf < 2; mf++) {
        const int rloc = wm * 32 + mf * 16 + g;
        const float sr0 = g_xs[row0 + rloc] * qsc, sr1 = g_xs[row0 + rloc + 8] * qsc;
        float m0 = 0.f, m1 = 0.f;
#pragma unroll
        for (int nf = 0; nf < 4; nf++) {
            const int col = col0 + wn * 32 + nf * 8 + tig * 2;
            const float sc0 = g_ws[col], sc1 = g_ws[col + 1];
            m0 = fmaxf(m0, fabsf(sr0 * sc0 * (16384.f * (float)hh[mf][nf][0] + 128.f * (float)cx[mf][nf][0])));
            m0 = fmaxf(m0, fabsf(sr0 * sc1 * (16384.f * (float)hh[mf][nf][1] + 128.f * (float)cx[mf][nf][1])));
            m1 = fmaxf(m1, fabsf(sr1 * sc0 * (16384.f * (float)hh[mf][nf][2] + 128.f * (float)cx[mf][nf][2])));
            m1 = fmaxf(m1, fabsf(sr1 * sc1 * (16384.f * (float)hh[mf][nf][3] + 128.f * (float)cx[mf][nf][3])));
        }
        atomicMax(&smax_i[rloc][half],     __float_as_int(m0));
        atomicMax(&smax_i[rloc + 8][half], __float_as_int(m1));
    }
    __syncthreads();

    const int head2 = (col0 - which * DIMC) >> 6;
    if (t < 256) {
        const int r = t >> 1, hf = t & 1;
        const float mx = __int_as_float(smax_i[r][hf]);
        const int grow = row0 + r, b = grow >> 10, n = grow & 1023;
        const int z = b * HEADS + head2 + hf;
        (which ? g_ks : g_qs)[z * NN + n] = mx * (1.f / 16256.f);
        sminv[r][hf] = mx > 0.f ? 16256.f / mx : 0.f;
    }
    __syncthreads();

    int8_t* dh = which ? g_kih : g_qih;
    int8_t* dl = which ? g_kil : g_qil;
#pragma unroll
    for (int mf = 0; mf < 2; mf++) {
        const int rloc = wm * 32 + mf * 16 + g;
        const float sr0 = g_xs[row0 + rloc] * qsc, sr1 = g_xs[row0 + rloc + 8] * qsc;
        const float inv0 = sminv[rloc][half], inv1 = sminv[rloc + 8][half];
        const int grow0 = row0 + rloc;
        const int b0 = grow0 >> 10, n0 = grow0 & 1023;
        const int z = b0 * HEADS + head2 + half;
        const size_t base0 = ((size_t)z * NN + n0) * HD;
        const size_t base1 = ((size_t)z * NN + n0 + 8) * HD;
#pragma unroll
        for (int nf = 0; nf < 4; nf++) {
            const int col = col0 + wn * 32 + nf * 8 + tig * 2;
            const int d = dbase + nf * 8 + tig * 2;
            const float sc0 = g_ws[col], sc1 = g_ws[col + 1];
            const float v00 = sr0 * sc0 * (16384.f * (float)hh[mf][nf][0] + 128.f * (float)cx[mf][nf][0]);
            const float v01 = sr0 * sc1 * (16384.f * (float)hh[mf][nf][1] + 128.f * (float)cx[mf][nf][1]);
            const float v10 = sr1 * sc0 * (16384.f * (float)hh[mf][nf][2] + 128.f * (float)cx[mf][nf][2]);
            const float v11 = sr1 * sc1 * (16384.f * (float)hh[mf][nf][3] + 128.f * (float)cx[mf][nf][3]);
            float q0 = v00 * inv0, q1 = v01 * inv0, q2 = v10 * inv1, q3 = v11 * inv1;
            float h0 = rintf(q0 * (1.f / 128.f)), h1 = rintf(q1 * (1.f / 128.f));
            float h2 = rintf(q2 * (1.f / 128.f)), h3 = rintf(q3 * (1.f / 128.f));
            *(char2*)&dh[base0 + d] = make_char2((signed char)h0, (signed char)h1);
            *(char2*)&dl[base0 + d] = make_char2((signed char)rintf(q0 - 128.f * h0),
                                                 (signed char)rintf(q1 - 128.f * h1));
            *(char2*)&dh[base1 + d] = make_char2((signed char)h2, (signed char)h3);
            *(char2*)&dl[base1 + d] = make_char2((signed char)rintf(q2 - 128.f * h2),
                                                 (signed char)rintf(q3 - 128.f * h3));
        }
    }
}

// ================= scores: persistent-q, fp16 S output =================
__global__ void __launch_bounds__(512, 1) k_scores_i8()
{
    extern __shared__ __align__(16) int8_t smi[];
    const uint32_t sb = (uint32_t)__cvta_generic_to_shared(smi);
    const int t = threadIdx.x, lane = t & 31, wid = t >> 5;
    const int wm = wid >> 2, wn = wid & 3;
    const int z = blockIdx.y;
    const int row0 = blockIdx.x * 128;

    const int qrow = t >> 2, qseg = t & 3;
    {
        const size_t src = ((size_t)z * NN + row0 + qrow) * HD + qseg * 16;
        const uint32_t d = sb + (uint32_t)(qrow * 80 + qseg * 16);
        cpa16(d,         g_qih + src);
        cpa16(d + 10240, g_qil + src);
    }
    cpa_commit();
    auto kissue = [&](int ct) {
        const size_t src = ((size_t)z * NN + ct * 128 + qrow) * HD + qseg * 16;
        const uint32_t d = sb + 20480 + (uint32_t)((ct & 1) * 20480 + qrow * 80 + qseg * 16);
        cpa16(d,         g_kih + src);
        cpa16(d + 10240, g_kil + src);
        cpa_commit();
    };
    kissue(0);

    asm volatile("cp.async.wait_group 1;");
    __syncthreads();
    uint32_t qah[2][2][4], qal[2][2][4];
#pragma unroll
    for (int s2 = 0; s2 < 2; s2++)
#pragma unroll
        for (int mf = 0; mf < 2; mf++) {
            const int m0 = wm * 32 + mf * 16;
            const uint32_t ad = sb + (uint32_t)((m0 + (lane & 15)) * 80) + s2 * 32 + ((lane >> 4) & 1) * 16;
            ldm_x4(qah[s2][mf], ad);
            ldm_x4(qal[s2][mf], ad + 10240);
        }

    const float* sq = g_qs + (size_t)z * NN;
    const float* sk = g_ks + (size_t)z * NN;
    __half* S = g_Sh + (size_t)z * NN * NN;
    const int g = lane >> 2, tig = lane & 3;

    for (int ct = 0; ct < 8; ct++) {
        if (ct + 1 < 8) { kissue(ct + 1); asm volatile("cp.async.wait_group 1;"); }
        else asm volatile("cp.async.wait_group 0;");
        __syncthreads();
        int hh[2][4][4] = {}, cx[2][4][4] = {};
        const uint32_t sK = sb + 20480 + (uint32_t)((ct & 1) * 20480);
#pragma unroll
        for (int s2 = 0; s2 < 2; s2++) {
#pragma unroll
            for (int nf = 0; nf < 4; nf++) {
                const int n0 = wn * 32 + nf * 8;
                const uint32_t bd = sK + (uint32_t)((n0 + (lane & 7)) * 80) + s2 * 32 + ((lane >> 3) & 1) * 16;
                uint32_t bh[2], bl[2];
                ldm_x2(bh, bd);
                ldm_x2(bl, bd + 10240);
#pragma unroll
                for (int mf = 0; mf < 2; mf++) {
                    imma16832(hh[mf][nf], qah[s2][mf], bh);
                    imma16832(cx[mf][nf], qah[s2][mf], bl);
                    imma16832(cx[mf][nf], qal[s2][mf], bh);
                }
            }
        }
        __syncthreads();
        const int col0 = ct * 128;
#pragma unroll
        for (int mf = 0; mf < 2; mf++) {
            const int row = row0 + wm * 32 + mf * 16 + g;
            const float sr0 = sq[row], sr1 = sq[row + 8];
#pragma unroll
            for (int nf = 0; nf < 4; nf++) {
                const int col = col0 + wn * 32 + nf * 8 + tig * 2;
                const float sc0 = sk[col], sc1 = sk[col + 1];
                *(__half2*)&S[(size_t)row * NN + col] = __floats2half2_rn(
                    sr0 * sc0 * (16384.f * (float)hh[mf][nf][0] + 128.f * (float)cx[mf][nf][0]),
                    sr0 * sc1 * (16384.f * (float)hh[mf][nf][1] + 128.f * (float)cx[mf][nf][1]));
                *(__half2*)&S[(size_t)(row + 8) * NN + col] = __floats2half2_rn(
                    sr1 * sc0 * (16384.f * (float)hh[mf][nf][2] + 128.f * (float)cx[mf][nf][2]),
                    sr1 * sc1 * (16384.f * (float)hh[mf][nf][3] + 128.f * (float)cx[mf][nf][3]));
            }
        }
    }
}

// ================= out = O @ Wout^T + bias =================
__global__ void __launch_bounds__(512, 1) k_out_i8(const float* __restrict__ bias,
                                                   float* __restrict__ out)
{
    const int row0 = blockIdx.y * 128, col0 = blockIdx.x * 128;
    int hh[2][4][4] = {}, cx[2][4][4] = {};
    gemm_i8_128<4>(g_Oih + (size_t)row0 * DIMC, g_Oil + (size_t)row0 * DIMC, DIMC,
                   g_woih + (size_t)col0 * DIMC, g_woil + (size_t)col0 * DIMC, DIMC,
                   DIMC, hh, cx);
    const int lane = threadIdx.x & 31, wid = threadIdx.x >> 5;
    const int wm = wid >> 2, wn = wid & 3, g = lane >> 2, tig = lane & 3;
#pragma unroll
    for (int mf = 0; mf < 2; mf++) {
        const int row = row0 + wm * 32 + mf * 16 + g;
        const float sr0 = g_Os[row], sr1 = g_Os[row + 8];
#pragma unroll
        for (int nf = 0; nf < 4; nf++) {
            const int col = col0 + wn * 32 + nf * 8 + tig * 2;
            const float sc0 = g_wos[col], sc1 = g_wos[col + 1];
            const float b0 = bias[col], b1 = bias[col + 1];
            *(float2*)&out[(size_t)row * DIMC + col] = make_float2(
                fmaf(sr0 * sc0, 16384.f * (float)hh[mf][nf][0] + 128.f * (float)cx[mf][nf][0], b0),
                fmaf(sr0 * sc1, 16384.f * (float)hh[mf][nf][1] + 128.f * (float)cx[mf][nf][1], b1));
            *(float2*)&out[(size_t)(row + 8) * DIMC + col] = make_float2(
                fmaf(sr1 * sc0, 16384.f * (float)hh[mf][nf][2] + 128.f * (float)cx[mf][nf][2], b0),
                fmaf(sr1 * sc1, 16384.f * (float)hh[mf][nf][3] + 128.f * (float)cx[mf][nf][3], b1));
        }
    }
}

// ---------------- int8 A@V (fused Av col-max) and A@(A@V) ----------------
__global__ void __launch_bounds__(256, 2) k_av_i8()
{
    __shared__ int scol[64];
    const int z = blockIdx.z;
    const int row0 = blockIdx.y * 128;
    int hh[2][4][4] = {}, cx[2][4][4] = {};
    gemm_i8_64(g_Aih + (size_t)z * NN * NN + (size_t)row0 * NN,
               g_Ail + (size_t)z * NN * NN + (size_t)row0 * NN,
               g_vTih + (size_t)z * HD * NN,
               g_vTil + (size_t)z * HD * NN, NN, hh, cx);
    const int t = threadIdx.x;
    const int lane = t & 31, wid = t >> 5;
    const int wm = wid >> 1, wn = wid & 1, g = lane >> 2, tig = lane & 3;
    float* Av = g_Av + (size_t)z * NN * HD;

    if (t < 64) scol[t] = 0;
    __syncthreads();

#pragma unroll
    for (int mf = 0; mf < 2; mf++) {
        const int row = row0 + wm * 32 + mf * 16 + g;
        const float sr0 = g_As[(size_t)z * NN + row], sr1 = g_As[(size_t)z * NN + row + 8];
#pragma unroll
        for (int nf = 0; nf < 4; nf++) {
            const int col = wn * 32 + nf * 8 + tig * 2;
            const float sc0 = g_vTs[z * HD + col], sc1 = g_vTs[z * HD + col + 1];
            const float v00 = sr0 * sc0 * (16384.f * (float)hh[mf][nf][0] + 128.f * (float)cx[mf][nf][0]);
            const float v01 = sr0 * sc1 * (16384.f * (float)hh[mf][nf][1] + 128.f * (float)cx[mf][nf][1]);
            const float v10 = sr1 * sc0 * (16384.f * (float)hh[mf][nf][2] + 128.f * (float)cx[mf][nf][2]);
            const float v11 = sr1 * sc1 * (16384.f * (float)hh[mf][nf][3] + 128.f * (float)cx[mf][nf][3]);
            *(float2*)&Av[(size_t)row * HD + col]       = make_float2(v00, v01);
            *(float2*)&Av[(size_t)(row + 8) * HD + col] = make_float2(v10, v11);
            atomicMax(&scol[col],     __float_as_int(fmaxf(fabsf(v00), fabsf(v10))));
            atomicMax(&scol[col + 1], __float_as_int(fmaxf(fabsf(v01), fabsf(v11))));
        }
    }
    __syncthreads();
    if (t < 64) atomicMax(&g_AvTmax[z * HD + t], (unsigned)scol[t]);
}

__global__ void __launch_bounds__(256, 2) k_aav_i8(const float* __restrict__ lamb)
{
    const int z = blockIdx.z, b = z / HEADS, h = z % HEADS;
    const int row0 = blockIdx.y * 128;
    int hh[2][4][4] = {}, cx[2][4][4] = {};
    gemm_i8_64(g_Aih + (size_t)z * NN * NN + (size_t)row0 * NN,
               g_Ail + (size_t)z * NN * NN + (size_t)row0 * NN,
               g_AvTih + (size_t)z * HD * NN,
               g_AvTil + (size_t)z * HD * NN, NN, hh, cx);
    const float lam = lamb[h];
    const float c1 = 1.f - 2.f * lam, c3 = 3.f * lam;
    const int lane = threadIdx.x & 31, wid = threadIdx.x >> 5;
    const int wm = wid >> 1, wn = wid & 1, g = lane >> 2, tig = lane & 3;
    const float* Av = g_Av + (size_t)z * NN * HD;
#pragma unroll
    for (int mf = 0; mf < 2; mf++) {
        const int row = row0 + wm * 32 + mf * 16 + g;
        const float sr0 = g_As[(size_t)z * NN + row], sr1 = g_As[(size_t)z * NN + row + 8];
#pragma unroll
        for (int nf = 0; nf < 4; nf++) {
            const int col = wn * 32 + nf * 8 + tig * 2;
            const float sc0 = g_AvTs[z * HD + col], sc1 = g_AvTs[z * HD + col + 1];
            const float r00 = sr0 * sc0 * (16384.f * (float)hh[mf][nf][0] + 128.f * (float)cx[mf][nf][0]);
            const float r01 = sr0 * sc1 * (16384.f * (float)hh[mf][nf][1] + 128.f * (float)cx[mf][nf][1]);
            const float r10 = sr1 * sc0 * (16384.f * (float)hh[mf][nf][2] + 128.f * (float)cx[mf][nf][2]);
            const float r11 = sr1 * sc1 * (16384.f * (float)hh[mf][nf][3] + 128.f * (float)cx[mf][nf][3]);
            float2 av0 = *(const float2*)&Av[(size_t)row * HD + col];
            float2 av1 = *(const float2*)&Av[(size_t)(row + 8) * HD + col];
            const size_t oi0 = ((size_t)b * NN + row) * DIMC + h * HD + col;
            const size_t oi1 = ((size_t)b * NN + row + 8) * DIMC + h * HD + col;
            *(float2*)&g_O[oi0] = make_float2(fmaf(c3, r00, c1 * av0.x), fmaf(c3, r01, c1 * av0.y));
            *(float2*)&g_O[oi1] = make_float2(fmaf(c3, r10, c1 * av1.x), fmaf(c3, r11, c1 * av1.y));
        }
    }
}

// ---------------- register-resident L-mix -> softmax -> W-mix -> int8 A quant ----------------
__global__ void __launch_bounds__(512) k_mix(const float* __restrict__ Lw,
                                             const float* __restrict__ Lb,
                                             const float* __restrict__ Ww,
                                             const float* __restrict__ Wb)
{
    __shared__ float sL[144], sW[144], sbl[12], sbw[12];
    __shared__ float red[12][16];
    __shared__ float gmax[12], ginv[12], sAinv[12];

    const int tid = threadIdx.x;
    const int b = blockIdx.x >> 10;
    const int n = blockIdx.x & 1023;

    if (tid < 144) { sL[tid] = Lw[tid]; sW[tid] = Ww[tid]; }
    if (tid < 12)  { sbl[tid] = Lb[tid]; sbw[tid] = Wb[tid]; }
    __syncthreads();

    const __half* Sbase = g_Sh + (size_t)b * HEADS * NN * NN + (size_t)n * NN;
    const int lane = tid & 31, wrp = tid >> 5;
    const int m = tid * 2;

    float2 s[12];
#pragma unroll
    for (int h = 0; h < 12; h++)
        s[h] = __half22float2(*(const __half2*)&Sbase[(size_t)h * NN * NN + m]);

    float2 a[12];
#pragma unroll
    for (int g = 0; g < 12; g++) {
        float t0 = sbl[g], t1 = sbl[g];
#pragma unroll
        for (int h = 0; h < 12; h++) {
            t0 = fmaf(sL[g * 12 + h], s[h].x, t0);
            t1 = fmaf(sL[g * 12 + h], s[h].y, t1);
        }
        a[g] = make_float2(t0, t1);
    }
#pragma unroll
    for (int g = 0; g < 12; g++) {
        float v = fmaxf(a[g].x, a[g].y);
#pragma unroll
        for (int o = 16; o; o >>= 1) v = fmaxf(v, __shfl_xor_sync(0xffffffffu, v, o));
        if (lane == 0) red[g][wrp] = v;
    }
    __syncthreads();
    if (tid < 12) {
        float v = red[tid][0];
#pragma unroll
        for (int w = 1; w < 16; w++) v = fmaxf(v, red[tid][w]);
        gmax[tid] = v;
    }
    __syncthreads();

#pragma unroll
    for (int g = 0; g < 12; g++) {
        a[g].x = __expf(a[g].x - gmax[g]);
        a[g].y = __expf(a[g].y - gmax[g]);
    }
#pragma unroll
    for (int g = 0; g < 12; g++) {
        float v = a[g].x + a[g].y;
#pragma unroll
        for (int o = 16; o; o >>= 1) v += __shfl_xor_sync(0xffffffffu, v, o);
        if (lane == 0) red[g][wrp] = v;
    }
    __syncthreads();
    if (tid < 12) {
        float v = red[tid][0];
#pragma unroll
        for (int w = 1; w < 16; w++) v += red[tid][w];
        ginv[tid] = 1.f / v;
    }
    __syncthreads();

#pragma unroll
    for (int h = 0; h < 12; h++) {
        s[h].x = a[h].x * ginv[h];
        s[h].y = a[h].y * ginv[h];
    }
#pragma unroll
    for (int g = 0; g < 12; g++) {
        float t0 = sbw[g], t1 = sbw[g];
#pragma unroll
        for (int h = 0; h < 12; h++) {
            t0 = fmaf(sW[g * 12 + h], s[h].x, t0);
            t1 = fmaf(sW[g * 12 + h], s[h].y, t1);
        }
        a[g] = make_float2(t0, t1);
    }
#pragma unroll
    for (int g = 0; g < 12; g++) {
        float v = fmaxf(fabsf(a[g].x), fabsf(a[g].y));
#pragma unroll
        for (int o = 16; o; o >>= 1) v = fmaxf(v, __shfl_xor_sync(0xffffffffu, v, o));
        if (lane == 0) red[g][wrp] = v;
    }
    __syncthreads();
    if (tid < 12) {
        float v = red[tid][0];
#pragma unroll
        for (int w = 1; w < 16; w++) v = fmaxf(v, red[tid][w]);
        g_As[((size_t)b * HEADS + tid) * NN + n] = v * (1.f / 16256.f);
        sAinv[tid] = v > 0.f ? 16256.f / v : 0.f;
    }
    __syncthreads();

    const size_t abase = (size_t)b * HEADS * NN * NN + (size_t)n * NN;
#pragma unroll
    for (int g = 0; g < 12; g++) {
        const float inv = sAinv[g];
        float q0 = a[g].x * inv, q1 = a[g].y * inv;
        float h0 = rintf(q0 * (1.f / 128.f)), h1 = rintf(q1 * (1.f / 128.f));
        float l0 = rintf(q0 - 128.f * h0),    l1 = rintf(q1 - 128.f * h1);
        const size_t o = abase + (size_t)g * NN * NN + m;
        *(char2*)&g_Aih[o] = make_char2((signed char)h0, (signed char)h1);
        *(char2*)&g_Ail[o] = make_char2((signed char)l0, (signed char)l1);
    }
}

// ---------------- launch ----------------
extern "C" void kernel_launch(void* const* d_in, const int* in_sizes, int n_in,
                              void* d_out, int out_size)
{
    (void)in_sizes; (void)n_in; (void)out_size;
    const float* x      = (const float*)d_in[0];
    const float* qkv_w  = (const float*)d_in[1];
    const float* Lw     = (const float*)d_in[2];
    const float* Lb     = (const float*)d_in[3];
    const float* Ww     = (const float*)d_in[4];
    const float* Wb     = (const float*)d_in[5];
    const float* lamb   = (const float*)d_in[6];
    const float* Wout   = (const float*)d_in[7];
    const float* bout   = (const float*)d_in[8];
    float* out = (float*)d_out;

    const int I8Q_SMEM = 98304, I8S_SMEM = 61440, I8_SMEM = 73728;
    cudaFuncSetAttribute(k_qkv_i8,    cudaFuncAttributeMaxDynamicSharedMemorySize, I8Q_SMEM);
    cudaFuncSetAttribute(k_scores_i8, cudaFuncAttributeMaxDynamicSharedMemorySize, I8S_SMEM);
    cudaFuncSetAttribute(k_out_i8,    cudaFuncAttributeMaxDynamicSharedMemorySize, I8Q_SMEM);
    cudaFuncSetAttribute(k_av_i8,     cudaFuncAttributeMaxDynamicSharedMemorySize, I8_SMEM);
    cudaFuncSetAttribute(k_aav_i8,    cudaFuncAttributeMaxDynamicSharedMemorySize, I8_SMEM);

    int8_t *oih, *oil;
    float *os, *gO;
    unsigned *vtm, *avtm;
    cudaGetSymbolAddress((void**)&oih,  g_Oih);  cudaGetSymbolAddress((void**)&oil,  g_Oil);
    cudaGetSymbolAddress((void**)&os,   g_Os);
    cudaGetSymbolAddress((void**)&gO,   g_O);
    cudaGetSymbolAddress((void**)&vtm,  g_vTmax); cudaGetSymbolAddress((void**)&avtm, g_AvTmax);

    // 0) quantize all fp32 operands (x, qkv_w, Wout) in one launch
    k_quant_all<<<NB * NN + 3 * DIMC + DIMC, 256>>>(x, qkv_w, Wout);
    // 1) qkv: q/k quantized in-epilogue; V -> fp32 + fused per-(z,d) max
    k_qkv_i8<<<dim3(LDQKV / 128, (NB * NN) / 128), 512, I8Q_SMEM>>>();
    // 2) V^T quantize+transpose (max already in g_vTmax)
    k_tqq<<<dim3(8, NZ), 256>>>(0, vtm);
    // 3) scores (int8x3, persistent-q, fp16 S)
    k_scores_i8<<<dim3(NN / 128, NZ), 512, I8S_SMEM>>>();
    // 4) mix + softmax + mix -> A int8 planes (register-resident)
    k_mix<<<NB * NN, 512>>>(Lw, Lb, Ww, Wb);
    // 5) Av = A @ v (int8x3) + fused per-(z,d) max
    k_av_i8<<<dim3(1, NN / 128, NZ), 256, I8_SMEM>>>();
    // 6) Av^T quantize+transpose
    k_tqq<<<dim3(8, NZ), 256>>>(1, avtm);
    // 7) O = (1-2λ)Av + 3λ A@Av
    k_aav_i8<<<dim3(1, NN / 128, NZ), 256, I8_SMEM>>>(lamb);
    // 8) quantize O rows; final projection
    k_quant<<<NB * NN, 256>>>(gO, DIMC, oih, oil, os);
    k_out_i8<<<dim3(DIMC / 128, (NB * NN) / 128), 512, I8Q_SMEM>>>(bout, out);
}